// round 3
// baseline (speedup 1.0000x reference)
#include <cuda_runtime.h>
#include <math.h>

#define Bk 8
#define Lk 1024
#define Ek 1024
#define Hk 16
#define Dk 64
#define BLk (Bk*Lk)

// Scratch (device globals — no allocation at kernel_launch time)
__device__ float g_q[(size_t)Bk*Lk*Ek];
__device__ float g_k[(size_t)Bk*Lk*Ek];
__device__ float g_v[(size_t)Bk*Lk*Ek];
__device__ float g_att[(size_t)Bk*Lk*Ek];

// ---------------------------------------------------------------------------
// Per-head projection: out[b,l,h,e] = sum_d in[b,l,h*D+d] * W[h,e,d]
// One block per (b,h, 64-row l-tile). 64x64x64 GEMM per block.
// ---------------------------------------------------------------------------
__global__ __launch_bounds__(256) void proj_kernel(const float* __restrict__ in,
                                                   const float* __restrict__ W,
                                                   int which) {
    __shared__ float Xs[64][65];
    __shared__ float Ws[64][65];
    float* out = (which == 0) ? g_q : (which == 1) ? g_k : g_v;

    int bh = blockIdx.y;
    int b = bh / Hk, h = bh % Hk;
    int l0 = blockIdx.x * 64;
    int tx = threadIdx.x, ty = threadIdx.y;
    int tid = ty * 16 + tx;

    const float* inp = in + ((size_t)b * Lk + l0) * Ek + h * Dk;
    const float* Wp  = W + (size_t)h * Dk * Dk;

    for (int idx = tid; idx < 64 * 64; idx += 256) {
        int r = idx >> 6, d = idx & 63;
        Xs[r][d] = inp[(size_t)r * Ek + d];
        Ws[r][d] = Wp[idx];          // Ws[e][d]
    }
    __syncthreads();

    float acc[4][4] = {};
    #pragma unroll 16
    for (int d = 0; d < 64; d++) {
        float a[4], bb[4];
        #pragma unroll
        for (int i = 0; i < 4; i++) a[i]  = Xs[ty + 16 * i][d];
        #pragma unroll
        for (int j = 0; j < 4; j++) bb[j] = Ws[tx + 16 * j][d];
        #pragma unroll
        for (int i = 0; i < 4; i++)
            #pragma unroll
            for (int j = 0; j < 4; j++)
                acc[i][j] += a[i] * bb[j];
    }

    float* op = out + ((size_t)b * Lk + l0) * Ek + h * Dk;
    #pragma unroll
    for (int i = 0; i < 4; i++)
        #pragma unroll
        for (int j = 0; j < 4; j++)
            op[(size_t)(ty + 16 * i) * Ek + tx + 16 * j] = acc[i][j];
}

// ---------------------------------------------------------------------------
// Flash attention per (b,h), q-tile of 64 rows, streaming K/V tiles of 64.
// 8 warps, each warp owns 8 q-rows; lane covers score cols {lane, lane+32}
// and output dims {lane, lane+32}. PV done via warp shuffles (no P in smem).
// ---------------------------------------------------------------------------
__global__ __launch_bounds__(256) void attn_kernel(const int* __restrict__ mask) {
    __shared__ float Qs[64][65];
    __shared__ float Ks[64][65];
    __shared__ float Vs[64][65];

    int bh = blockIdx.y;
    int b = bh / Hk, h = bh % Hk;
    int q0 = blockIdx.x * 64;
    int tid = threadIdx.x;
    int warp = tid >> 5, lane = tid & 31;
    const float scale = 0.125f;  // 1/sqrt(64)

    for (int idx = tid; idx < 64 * 64; idx += 256) {
        int r = idx >> 6, d = idx & 63;
        Qs[r][d] = g_q[((size_t)b * Lk + q0 + r) * Ek + h * Dk + d];
    }

    float m[8], lsum[8], O0[8], O1[8];
    #pragma unroll
    for (int r = 0; r < 8; r++) { m[r] = -1e30f; lsum[r] = 0.f; O0[r] = 0.f; O1[r] = 0.f; }

    const int* mbase = mask + (size_t)b * Lk * Lk;

    for (int kt = 0; kt < Lk / 64; kt++) {
        int k0 = kt * 64;
        __syncthreads();
        for (int idx = tid; idx < 64 * 64; idx += 256) {
            int r = idx >> 6, d = idx & 63;
            size_t off = ((size_t)b * Lk + k0 + r) * Ek + h * Dk + d;
            Ks[r][d] = g_k[off];
            Vs[r][d] = g_v[off];
        }
        __syncthreads();

        #pragma unroll
        for (int r = 0; r < 8; r++) {
            int row = warp * 8 + r;
            float s0 = 0.f, s1 = 0.f;
            #pragma unroll 16
            for (int d = 0; d < 64; d++) {
                float qv = Qs[row][d];
                s0 += qv * Ks[lane][d];
                s1 += qv * Ks[lane + 32][d];
            }
            const int* mrow = mbase + (size_t)(q0 + row) * Lk + k0;
            if (mrow[lane] == 0)      s0 = -1e20f;
            if (mrow[lane + 32] == 0) s1 = -1e20f;
            s0 *= scale; s1 *= scale;

            float mx = fmaxf(s0, s1);
            #pragma unroll
            for (int off = 16; off > 0; off >>= 1)
                mx = fmaxf(mx, __shfl_xor_sync(0xffffffffu, mx, off));
            float mnew = fmaxf(m[r], mx);

            float p0 = __expf(s0 - mnew);
            float p1 = __expf(s1 - mnew);
            float rs = p0 + p1;
            #pragma unroll
            for (int off = 16; off > 0; off >>= 1)
                rs += __shfl_xor_sync(0xffffffffu, rs, off);

            float alpha = __expf(m[r] - mnew);
            m[r] = mnew;
            lsum[r] = lsum[r] * alpha + rs;

            float acc0 = 0.f, acc1 = 0.f;
            #pragma unroll 8
            for (int kk = 0; kk < 32; kk++) {
                float pk = __shfl_sync(0xffffffffu, p0, kk);
                acc0 += pk * Vs[kk][lane];
                acc1 += pk * Vs[kk][lane + 32];
            }
            #pragma unroll 8
            for (int kk = 0; kk < 32; kk++) {
                float pk = __shfl_sync(0xffffffffu, p1, kk);
                acc0 += pk * Vs[kk + 32][lane];
                acc1 += pk * Vs[kk + 32][lane + 32];
            }
            O0[r] = O0[r] * alpha + acc0;
            O1[r] = O1[r] * alpha + acc1;
        }
    }

    #pragma unroll
    for (int r = 0; r < 8; r++) {
        int row = warp * 8 + r;
        float inv = 1.0f / lsum[r];
        size_t off = ((size_t)b * Lk + q0 + row) * Ek + h * Dk;
        g_att[off + lane]      = O0[r] * inv;
        g_att[off + lane + 32] = O1[r] * inv;
    }
}

// ---------------------------------------------------------------------------
// Output projection: out[m,n] = sum_k g_att[m,k] * Wo[n,k] + bo[n]
// M = B*L = 8192, N = K = 1024. 64x64 tiles, 4x4 register micro-tiles.
// ---------------------------------------------------------------------------
__global__ __launch_bounds__(256) void outproj_kernel(const float* __restrict__ Wo,
                                                      const float* __restrict__ bo,
                                                      float* __restrict__ out) {
    __shared__ float As[64][17];
    __shared__ float Bs[64][17];

    int n0 = blockIdx.x * 64;
    int m0 = blockIdx.y * 64;
    int tx = threadIdx.x, ty = threadIdx.y;
    int tid = ty * 16 + tx;

    float acc[4][4] = {};

    for (int k0 = 0; k0 < Ek; k0 += 16) {
        __syncthreads();
        for (int idx = tid; idx < 64 * 16; idx += 256) {
            int r = idx >> 4, kk = idx & 15;
            As[r][kk] = g_att[(size_t)(m0 + r) * Ek + k0 + kk];
            Bs[r][kk] = Wo[(size_t)(n0 + r) * Ek + k0 + kk];
        }
        __syncthreads();

        #pragma unroll
        for (int kk = 0; kk < 16; kk++) {
            float a[4], bb[4];
            #pragma unroll
            for (int i = 0; i < 4; i++) a[i]  = As[ty + 16 * i][kk];
            #pragma unroll
            for (int j = 0; j < 4; j++) bb[j] = Bs[tx + 16 * j][kk];
            #pragma unroll
            for (int i = 0; i < 4; i++)
                #pragma unroll
                for (int j = 0; j < 4; j++)
                    acc[i][j] += a[i] * bb[j];
        }
    }

    #pragma unroll
    for (int i = 0; i < 4; i++) {
        int mm = m0 + ty + 16 * i;
        #pragma unroll
        for (int j = 0; j < 4; j++) {
            int nn = n0 + tx + 16 * j;
            out[(size_t)mm * Ek + nn] = acc[i][j] + bo[nn];
        }
    }
}

// ---------------------------------------------------------------------------
extern "C" void kernel_launch(void* const* d_in, const int* in_sizes, int n_in,
                              void* d_out, int out_size) {
    const float* values = (const float*)d_in[0];
    const float* keys   = (const float*)d_in[1];
    const float* query  = (const float*)d_in[2];
    const int*   mask   = (const int*)d_in[3];
    // d_in[4] = size (scalar), compile-time constant here
    const float* Wv = (const float*)d_in[5];
    const float* Wk = (const float*)d_in[6];
    const float* Wq = (const float*)d_in[7];
    const float* Wo = (const float*)d_in[8];
    const float* bo = (const float*)d_in[9];
    float* out = (float*)d_out;

    dim3 pgrid(Lk / 64, Bk * Hk);
    dim3 pblock(16, 16);
    proj_kernel<<<pgrid, pblock>>>(query,  Wq, 0);
    proj_kernel<<<pgrid, pblock>>>(keys,   Wk, 1);
    proj_kernel<<<pgrid, pblock>>>(values, Wv, 2);

    dim3 agrid(Lk / 64, Bk * Hk);
    attn_kernel<<<agrid, 256>>>(mask);

    dim3 ogrid(Ek / 64, BLk / 64);
    outproj_kernel<<<ogrid, pblock>>>(Wo, bo, out);
}

// round 6
// speedup vs baseline: 2.0449x; 2.0449x over previous
#include <cuda_runtime.h>
#include <math.h>

#define Bk 8
#define Lk 1024
#define Ek 1024
#define Hk 16
#define Dk 64
#define BLk (Bk*Lk)

// Scratch (device globals — no allocation at kernel_launch time)
__device__ float g_q[(size_t)Bk*Lk*Ek];
__device__ float g_k[(size_t)Bk*Lk*Ek];
__device__ float g_v[(size_t)Bk*Lk*Ek];
__device__ float g_att[(size_t)Bk*Lk*Ek];

// ---------------------------------------------------------------------------
// Per-head projection (all three in one launch, which = blockIdx.z):
// out[b,l,h,e] = sum_d in[b,l,h*D+d] * W[h,e,d]
// One block per (b,h, 64-row l-tile). 64x64x64 GEMM, float4-vectorized.
// ---------------------------------------------------------------------------
__global__ __launch_bounds__(256) void proj_kernel(const float* __restrict__ vin,
                                                   const float* __restrict__ kin,
                                                   const float* __restrict__ qin,
                                                   const float* __restrict__ Wv,
                                                   const float* __restrict__ Wk,
                                                   const float* __restrict__ Wq) {
    __shared__ float Xs[64 * 64];   // stride 64 (broadcast reads)
    __shared__ float Ws[64 * 68];   // stride 68 (conflict-free float4 reads)

    int which = blockIdx.z;
    const float* in = (which == 0) ? qin : (which == 1) ? kin : vin;
    const float* W  = (which == 0) ? Wq  : (which == 1) ? Wk  : Wv;
    float* out      = (which == 0) ? g_q : (which == 1) ? g_k : g_v;

    int bh = blockIdx.y;
    int b = bh >> 4, h = bh & 15;
    int l0 = blockIdx.x * 64;
    int tid = threadIdx.x;
    int tx = tid & 15, ty = tid >> 4;

    const float* inp = in + ((size_t)b * Lk + l0) * Ek + h * Dk;
    const float* Wp  = W + (size_t)h * Dk * Dk;

    #pragma unroll
    for (int i = 0; i < 4; i++) {
        int idx = tid + 256 * i;            // 0..1023 float4 slots
        int r = idx >> 4, c = (idx & 15) * 4;
        *(float4*)&Xs[r * 64 + c] = *(const float4*)&inp[(size_t)r * Ek + c];
        *(float4*)&Ws[r * 68 + c] = *(const float4*)&Wp[r * 64 + c];
    }
    __syncthreads();

    float acc[4][4] = {};
    #pragma unroll 4
    for (int d4 = 0; d4 < 64; d4 += 4) {
        float4 a[4], bb[4];
        #pragma unroll
        for (int i = 0; i < 4; i++) a[i]  = *(const float4*)&Xs[(ty + 16 * i) * 64 + d4];
        #pragma unroll
        for (int j = 0; j < 4; j++) bb[j] = *(const float4*)&Ws[(tx + 16 * j) * 68 + d4];
        #pragma unroll
        for (int i = 0; i < 4; i++)
            #pragma unroll
            for (int j = 0; j < 4; j++)
                acc[i][j] += a[i].x * bb[j].x + a[i].y * bb[j].y
                           + a[i].z * bb[j].z + a[i].w * bb[j].w;
    }

    float* op = out + ((size_t)b * Lk + l0) * Ek + h * Dk;
    #pragma unroll
    for (int i = 0; i < 4; i++)
        #pragma unroll
        for (int j = 0; j < 4; j++)
            op[(size_t)(ty + 16 * i) * Ek + tx + 16 * j] = acc[i][j];
}

// ---------------------------------------------------------------------------
// Flash attention per (b,h), q-tile 64 rows, k-tiles of 64. 8 warps, each
// warp owns 8 q-rows. Score phase: lane owns k-cols {lane, lane+32}, K value
// loaded once per d4 and reused across 8 rows (float4). PV: P is written into
// the (dead) K buffer, lane owns dims {2*lane, 2*lane+1}, float4 P + float2 V.
// ---------------------------------------------------------------------------
__global__ __launch_bounds__(256) void attn_kernel(const int* __restrict__ mask) {
    extern __shared__ float sm[];
    float* Qs = sm;                  // [64][64]
    float* Ks = sm + 64 * 64;        // [64][68], aliased as P after scores
    float* Vs = Ks + 64 * 68;        // [64][68]

    int bh = blockIdx.y;
    int b = bh >> 4, h = bh & 15;
    int q0 = blockIdx.x * 64;
    int tid = threadIdx.x;
    int warp = tid >> 5, lane = tid & 31;
    const float scale = 0.125f;      // 1/sqrt(64)

    // Load Q tile (stride 64; compute reads are warp-broadcast)
    const float* qbase = g_q + ((size_t)b * Lk + q0) * Ek + h * Dk;
    #pragma unroll
    for (int i = 0; i < 4; i++) {
        int idx = tid + 256 * i;
        int r = idx >> 4, c = (idx & 15) * 4;
        *(float4*)&Qs[r * 64 + c] = *(const float4*)&qbase[(size_t)r * Ek + c];
    }

    float m[8], l[8], O[8][2];
    #pragma unroll
    for (int r = 0; r < 8; r++) {
        m[r] = -1e30f; l[r] = 0.f; O[r][0] = 0.f; O[r][1] = 0.f;
    }

    for (int kt = 0; kt < Lk / 64; kt++) {
        int k0 = kt * 64;
        __syncthreads();
        const float* kbase = g_k + ((size_t)b * Lk + k0) * Ek + h * Dk;
        const float* vbase = g_v + ((size_t)b * Lk + k0) * Ek + h * Dk;
        #pragma unroll
        for (int i = 0; i < 4; i++) {
            int idx = tid + 256 * i;
            int r = idx >> 4, c = (idx & 15) * 4;
            *(float4*)&Ks[r * 68 + c] = *(const float4*)&kbase[(size_t)r * Ek + c];
            *(float4*)&Vs[r * 68 + c] = *(const float4*)&vbase[(size_t)r * Ek + c];
        }
        __syncthreads();

        // ---- scores: s[r][col] for col in {lane, lane+32} ----
        float s0[8], s1[8];
        #pragma unroll
        for (int r = 0; r < 8; r++) { s0[r] = 0.f; s1[r] = 0.f; }

        const float* KA = &Ks[lane * 68];
        const float* KB = &Ks[(lane + 32) * 68];
        const float* QW = &Qs[(warp * 8) * 64];

        #pragma unroll 4
        for (int d4 = 0; d4 < 64; d4 += 4) {
            float4 ka = *(const float4*)&KA[d4];
            float4 kb = *(const float4*)&KB[d4];
            #pragma unroll
            for (int r = 0; r < 8; r++) {
                float4 q = *(const float4*)&QW[r * 64 + d4];
                s0[r] += q.x * ka.x + q.y * ka.y + q.z * ka.z + q.w * ka.w;
                s1[r] += q.x * kb.x + q.y * kb.y + q.z * kb.z + q.w * kb.w;
            }
        }

        // ---- mask + online softmax (per q-row, in registers) ----
        #pragma unroll
        for (int r = 0; r < 8; r++) {
            int qrow = q0 + warp * 8 + r;
            const int* mrow = mask + ((size_t)b * Lk + qrow) * Lk + k0;
            float v0 = (mrow[lane] == 0)      ? -1e20f : s0[r] * scale;
            float v1 = (mrow[lane + 32] == 0) ? -1e20f : s1[r] * scale;

            float mx = fmaxf(v0, v1);
            #pragma unroll
            for (int off = 16; off > 0; off >>= 1)
                mx = fmaxf(mx, __shfl_xor_sync(0xffffffffu, mx, off));
            float mnew = fmaxf(m[r], mx);

            float p0 = __expf(v0 - mnew);
            float p1 = __expf(v1 - mnew);
            float rs = p0 + p1;
            #pragma unroll
            for (int off = 16; off > 0; off >>= 1)
                rs += __shfl_xor_sync(0xffffffffu, rs, off);

            float alpha = __expf(m[r] - mnew);
            m[r] = mnew;
            l[r] = l[r] * alpha + rs;
            O[r][0] *= alpha; O[r][1] *= alpha;
            s0[r] = p0; s1[r] = p1;      // reuse registers as P
        }

        // All warps done reading K for scores -> safe to overwrite with P
        __syncthreads();
        #pragma unroll
        for (int r = 0; r < 8; r++) {
            int row = warp * 8 + r;
            Ks[row * 68 + lane]      = s0[r];
            Ks[row * 68 + lane + 32] = s1[r];
        }
        __syncwarp();

        // ---- PV: O[row][{2*lane, 2*lane+1}] += P[row][kk] * V[kk][dim] ----
        #pragma unroll
        for (int half = 0; half < 2; half++) {
            #pragma unroll 4
            for (int kk4 = 0; kk4 < 64; kk4 += 4) {
                float4 p[4];
                #pragma unroll
                for (int rr = 0; rr < 4; rr++)
                    p[rr] = *(const float4*)&Ks[(warp * 8 + half * 4 + rr) * 68 + kk4];
                #pragma unroll
                for (int t = 0; t < 4; t++) {
                    float2 v = *(const float2*)&Vs[(kk4 + t) * 68 + 2 * lane];
                    #pragma unroll
                    for (int rr = 0; rr < 4; rr++) {
                        float pt = ((const float*)&p[rr])[t];
                        O[half * 4 + rr][0] += pt * v.x;
                        O[half * 4 + rr][1] += pt * v.y;
                    }
                }
            }
        }
    }

    #pragma unroll
    for (int r = 0; r < 8; r++) {
        float inv = 1.0f / l[r];
        float2 o = make_float2(O[r][0] * inv, O[r][1] * inv);
        *(float2*)&g_att[((size_t)b * Lk + q0 + warp * 8 + r) * Ek + h * Dk + 2 * lane] = o;
    }
}

// ---------------------------------------------------------------------------
// Output projection: out[m,n] = sum_k g_att[m,k] * Wo[n,k] + bo[n]
// M = 8192, N = K = 1024. 64x64 tiles, BK=32, float4-vectorized.
// ---------------------------------------------------------------------------
__global__ __launch_bounds__(256) void outproj_kernel(const float* __restrict__ Wo,
                                                      const float* __restrict__ bo,
                                                      float* __restrict__ out) {
    __shared__ float As[64 * 32];   // stride 32 (broadcast reads)
    __shared__ float Bs[64 * 36];   // stride 36 (conflict-free float4 reads)

    int n0 = blockIdx.x * 64;
    int m0 = blockIdx.y * 64;
    int tid = threadIdx.x;
    int tx = tid & 15, ty = tid >> 4;

    float acc[4][4] = {};

    for (int k0 = 0; k0 < Ek; k0 += 32) {
        __syncthreads();
        #pragma unroll
        for (int i = 0; i < 2; i++) {
            int idx = tid + 256 * i;           // 0..511 float4 slots
            int r = idx >> 3, c = (idx & 7) * 4;
            *(float4*)&As[r * 32 + c] = *(const float4*)&g_att[(size_t)(m0 + r) * Ek + k0 + c];
            *(float4*)&Bs[r * 36 + c] = *(const float4*)&Wo[(size_t)(n0 + r) * Ek + k0 + c];
        }
        __syncthreads();

        #pragma unroll 4
        for (int k4 = 0; k4 < 32; k4 += 4) {
            float4 a[4], bb[4];
            #pragma unroll
            for (int i = 0; i < 4; i++) a[i]  = *(const float4*)&As[(ty + 16 * i) * 32 + k4];
            #pragma unroll
            for (int j = 0; j < 4; j++) bb[j] = *(const float4*)&Bs[(tx + 16 * j) * 36 + k4];
            #pragma unroll
            for (int i = 0; i < 4; i++)
                #pragma unroll
                for (int j = 0; j < 4; j++)
                    acc[i][j] += a[i].x * bb[j].x + a[i].y * bb[j].y
                               + a[i].z * bb[j].z + a[i].w * bb[j].w;
        }
    }

    #pragma unroll
    for (int i = 0; i < 4; i++) {
        int mm = m0 + ty + 16 * i;
        #pragma unroll
        for (int j = 0; j < 4; j++) {
            int nn = n0 + tx + 16 * j;
            out[(size_t)mm * Ek + nn] = acc[i][j] + bo[nn];
        }
    }
}

// ---------------------------------------------------------------------------
extern "C" void kernel_launch(void* const* d_in, const int* in_sizes, int n_in,
                              void* d_out, int out_size) {
    const float* values = (const float*)d_in[0];
    const float* keys   = (const float*)d_in[1];
    const float* query  = (const float*)d_in[2];
    const int*   mask   = (const int*)d_in[3];
    // d_in[4] = size (scalar), compile-time constant here
    const float* Wv = (const float*)d_in[5];
    const float* Wk = (const float*)d_in[6];
    const float* Wq = (const float*)d_in[7];
    const float* Wo = (const float*)d_in[8];
    const float* bo = (const float*)d_in[9];
    float* out = (float*)d_out;

    // attn needs 51200 B of dynamic smem (> 48K default)
    static const int ATTN_SMEM = (64 * 64 + 2 * 64 * 68) * 4;
    cudaFuncSetAttribute(attn_kernel, cudaFuncAttributeMaxDynamicSharedMemorySize, ATTN_SMEM);

    dim3 pgrid(Lk / 64, Bk * Hk, 3);
    proj_kernel<<<pgrid, 256>>>(values, keys, query, Wv, Wk, Wq);

    dim3 agrid(Lk / 64, Bk * Hk);
    attn_kernel<<<agrid, 256, ATTN_SMEM>>>(mask);

    dim3 ogrid(Ek / 64, BLk / 64);
    outproj_kernel<<<ogrid, 256>>>(Wo, bo, out);
}

// round 9
// speedup vs baseline: 4.1377x; 2.0234x over previous
#include <cuda_runtime.h>
#include <cuda_bf16.h>
#include <math.h>

#define Bk 8
#define Lk 1024
#define Ek 1024
#define Hk 16
#define Dk 64
#define BLk (Bk*Lk)

// hi/lo bf16 scratch (device globals — no allocation in kernel_launch)
__device__ __nv_bfloat16 g_qh[(size_t)Bk*Lk*Ek], g_ql[(size_t)Bk*Lk*Ek];
__device__ __nv_bfloat16 g_kh[(size_t)Bk*Lk*Ek], g_kl[(size_t)Bk*Lk*Ek];
__device__ __nv_bfloat16 g_vh[(size_t)Bk*Lk*Ek], g_vl[(size_t)Bk*Lk*Ek];
__device__ __nv_bfloat16 g_oh[(size_t)Bk*Lk*Ek], g_ol[(size_t)Bk*Lk*Ek];

// ---------------------------------------------------------------------------
// mma.sync m16n8k16 row.col bf16 -> f32 accumulate
// A frag (thread, g=lane>>2, t=lane&3): a0=(g,2t..2t+1) a1=(g+8,2t..) a2=(g,2t+8..) a3=(g+8,2t+8..)
// B frag: b0=(k=2t..2t+1, n=g) b1=(k=2t+8.., n=g)
// D frag: d0=(g,2t) d1=(g,2t+1) d2=(g+8,2t) d3=(g+8,2t+1)
// ---------------------------------------------------------------------------
__device__ __forceinline__ void mma16816(float* d, const unsigned* a, const unsigned* b) {
    asm volatile(
        "mma.sync.aligned.m16n8k16.row.col.f32.bf16.bf16.f32 "
        "{%0,%1,%2,%3}, {%4,%5,%6,%7}, {%8,%9}, {%0,%1,%2,%3};\n"
        : "+f"(d[0]), "+f"(d[1]), "+f"(d[2]), "+f"(d[3])
        : "r"(a[0]), "r"(a[1]), "r"(a[2]), "r"(a[3]), "r"(b[0]), "r"(b[1]));
}

__device__ __forceinline__ void split1(float x, __nv_bfloat16& h, __nv_bfloat16& l) {
    h = __float2bfloat16_rn(x);
    l = __float2bfloat16_rn(x - __bfloat162float(h));
}

// pack two adjacent values into bf16x2 hi and lo words
__device__ __forceinline__ void pack_split(float x, float y, unsigned& hi, unsigned& lo) {
    __nv_bfloat162 h = __floats2bfloat162_rn(x, y);
    float rx = x - __bfloat162float(h.x);
    float ry = y - __bfloat162float(h.y);
    __nv_bfloat162 l = __floats2bfloat162_rn(rx, ry);
    hi = *(unsigned*)&h; lo = *(unsigned*)&l;
}

// ---------------------------------------------------------------------------
// Per-head projection: out[l,e] = sum_d X[l,d] * W[e,d], 64x64x64 per block.
// which = blockIdx.z: 0=q, 1=k, 2=v. Writes hi/lo bf16 pairs to global.
// ---------------------------------------------------------------------------
__global__ __launch_bounds__(128) void proj_kernel(const float* __restrict__ vin,
                                                   const float* __restrict__ kin,
                                                   const float* __restrict__ qin,
                                                   const float* __restrict__ Wv,
                                                   const float* __restrict__ Wk,
                                                   const float* __restrict__ Wq) {
    __shared__ __nv_bfloat16 Xh[64*72], Xl[64*72], Wh[64*72], Wl[64*72];

    int which = blockIdx.z;
    const float* in = (which == 0) ? qin : (which == 1) ? kin : vin;
    const float* W  = (which == 0) ? Wq  : (which == 1) ? Wk  : Wv;
    __nv_bfloat16* outh = (which == 0) ? g_qh : (which == 1) ? g_kh : g_vh;
    __nv_bfloat16* outl = (which == 0) ? g_ql : (which == 1) ? g_kl : g_vl;

    int bh = blockIdx.y;
    int b = bh >> 4, h = bh & 15;
    int l0 = blockIdx.x * 64;
    int tid = threadIdx.x;
    int warp = tid >> 5, lane = tid & 31;
    int g = lane >> 2, tg = lane & 3;

    const float* inp = in + ((size_t)b * Lk + l0) * Ek + h * Dk;
    const float* Wp  = W + (size_t)h * Dk * Dk;

    #pragma unroll
    for (int i = 0; i < 8; i++) {
        int slot = tid + 128 * i;            // 1024 float4 slots
        int r = slot >> 4, c = (slot & 15) * 4;
        float4 x = *(const float4*)&inp[(size_t)r * Ek + c];
        split1(x.x, Xh[r*72+c+0], Xl[r*72+c+0]);
        split1(x.y, Xh[r*72+c+1], Xl[r*72+c+1]);
        split1(x.z, Xh[r*72+c+2], Xl[r*72+c+2]);
        split1(x.w, Xh[r*72+c+3], Xl[r*72+c+3]);
        float4 w = *(const float4*)&Wp[r * 64 + c];
        split1(w.x, Wh[r*72+c+0], Wl[r*72+c+0]);
        split1(w.y, Wh[r*72+c+1], Wl[r*72+c+1]);
        split1(w.z, Wh[r*72+c+2], Wl[r*72+c+2]);
        split1(w.w, Wh[r*72+c+3], Wl[r*72+c+3]);
    }
    __syncthreads();

    int mrow = warp * 16 + g;
    unsigned ah[4][4], al[4][4];
    #pragma unroll
    for (int ks = 0; ks < 4; ks++) {
        int c0 = ks * 16 + 2 * tg;
        ah[ks][0] = *(const unsigned*)&Xh[mrow*72 + c0];
        ah[ks][1] = *(const unsigned*)&Xh[(mrow+8)*72 + c0];
        ah[ks][2] = *(const unsigned*)&Xh[mrow*72 + c0 + 8];
        ah[ks][3] = *(const unsigned*)&Xh[(mrow+8)*72 + c0 + 8];
        al[ks][0] = *(const unsigned*)&Xl[mrow*72 + c0];
        al[ks][1] = *(const unsigned*)&Xl[(mrow+8)*72 + c0];
        al[ks][2] = *(const unsigned*)&Xl[mrow*72 + c0 + 8];
        al[ks][3] = *(const unsigned*)&Xl[(mrow+8)*72 + c0 + 8];
    }

    float acc[8][4] = {};
    #pragma unroll
    for (int ks = 0; ks < 4; ks++) {
        int c0 = ks * 16 + 2 * tg;
        #pragma unroll
        for (int nt = 0; nt < 8; nt++) {
            int brow = nt * 8 + g;
            unsigned bhf[2] = { *(const unsigned*)&Wh[brow*72 + c0],
                                *(const unsigned*)&Wh[brow*72 + c0 + 8] };
            unsigned blf[2] = { *(const unsigned*)&Wl[brow*72 + c0],
                                *(const unsigned*)&Wl[brow*72 + c0 + 8] };
            mma16816(acc[nt], ah[ks], bhf);
            mma16816(acc[nt], ah[ks], blf);
            mma16816(acc[nt], al[ks], bhf);
        }
    }

    size_t base0 = ((size_t)b * Lk + l0 + mrow) * Ek + h * Dk;
    size_t base1 = base0 + (size_t)8 * Ek;
    #pragma unroll
    for (int nt = 0; nt < 8; nt++) {
        int col = nt * 8 + 2 * tg;
        unsigned hi, lo;
        pack_split(acc[nt][0], acc[nt][1], hi, lo);
        *(unsigned*)&outh[base0 + col] = hi;
        *(unsigned*)&outl[base0 + col] = lo;
        pack_split(acc[nt][2], acc[nt][3], hi, lo);
        *(unsigned*)&outh[base1 + col] = hi;
        *(unsigned*)&outl[base1 + col] = lo;
    }
}

// ---------------------------------------------------------------------------
// Flash attention, tensor-core version. Block = 128 thr (4 warps), q-tile 64
// (16 rows/warp), k-tiles of 64. S = Q@K^T via bf16x3 mma (Q frags in regs),
// softmax on register S-fragments, P split hi/lo in registers -> A frags for
// P@V (V staged transposed). Writes att as hi/lo bf16.
// ---------------------------------------------------------------------------
__global__ __launch_bounds__(128) void attn_kernel(const int* __restrict__ mask) {
    extern __shared__ __nv_bfloat16 sm[];
    __nv_bfloat16* Qh  = sm;
    __nv_bfloat16* Ql  = sm + 4608;       // 64*72
    __nv_bfloat16* Kh  = sm + 2*4608;
    __nv_bfloat16* Kl  = sm + 3*4608;
    __nv_bfloat16* VTh = sm + 4*4608;
    __nv_bfloat16* VTl = sm + 5*4608;

    int bh = blockIdx.y;
    int b = bh >> 4, h = bh & 15;
    int q0 = blockIdx.x * 64;
    int tid = threadIdx.x;
    int warp = tid >> 5, lane = tid & 31;
    int g = lane >> 2, tg = lane & 3;
    const float scale = 0.125f;

    // stage Q tile (hi/lo) into smem
    {
        const __nv_bfloat16* qhp = g_qh + ((size_t)b * Lk + q0) * Ek + h * Dk;
        const __nv_bfloat16* qlp = g_ql + ((size_t)b * Lk + q0) * Ek + h * Dk;
        #pragma unroll
        for (int i = 0; i < 8; i++) {
            int slot = tid + 128 * i;           // 1024 uint2 slots (4 bf16)
            int r = slot >> 4, c = (slot & 15) * 4;
            *(uint2*)&Qh[r*72 + c] = *(const uint2*)&qhp[(size_t)r * Ek + c];
            *(uint2*)&Ql[r*72 + c] = *(const uint2*)&qlp[(size_t)r * Ek + c];
        }
    }
    __syncthreads();

    // hoist Q fragments to registers
    int mrow = warp * 16 + g;
    unsigned qfh[4][4], qfl[4][4];
    #pragma unroll
    for (int ks = 0; ks < 4; ks++) {
        int c0 = ks * 16 + 2 * tg;
        qfh[ks][0] = *(const unsigned*)&Qh[mrow*72 + c0];
        qfh[ks][1] = *(const unsigned*)&Qh[(mrow+8)*72 + c0];
        qfh[ks][2] = *(const unsigned*)&Qh[mrow*72 + c0 + 8];
        qfh[ks][3] = *(const unsigned*)&Qh[(mrow+8)*72 + c0 + 8];
        qfl[ks][0] = *(const unsigned*)&Ql[mrow*72 + c0];
        qfl[ks][1] = *(const unsigned*)&Ql[(mrow+8)*72 + c0];
        qfl[ks][2] = *(const unsigned*)&Ql[mrow*72 + c0 + 8];
        qfl[ks][3] = *(const unsigned*)&Ql[(mrow+8)*72 + c0 + 8];
    }

    float mrun0 = -1e30f, mrun1 = -1e30f, lrun0 = 0.f, lrun1 = 0.f;
    float O[8][4] = {};

    int qrow0 = q0 + mrow;
    int qrow1 = qrow0 + 8;
    const int* mb = mask + (size_t)b * Lk * Lk;

    for (int kt = 0; kt < Lk / 64; kt++) {
        int k0 = kt * 64;
        __syncthreads();
        {
            const __nv_bfloat16* khp = g_kh + ((size_t)b * Lk + k0) * Ek + h * Dk;
            const __nv_bfloat16* klp = g_kl + ((size_t)b * Lk + k0) * Ek + h * Dk;
            const __nv_bfloat16* vhp = g_vh + ((size_t)b * Lk + k0) * Ek + h * Dk;
            const __nv_bfloat16* vlp = g_vl + ((size_t)b * Lk + k0) * Ek + h * Dk;
            #pragma unroll
            for (int i = 0; i < 8; i++) {
                int slot = tid + 128 * i;
                int r = slot >> 4, c = (slot & 15) * 4;
                *(uint2*)&Kh[r*72 + c] = *(const uint2*)&khp[(size_t)r * Ek + c];
                *(uint2*)&Kl[r*72 + c] = *(const uint2*)&klp[(size_t)r * Ek + c];
                uint2 vh = *(const uint2*)&vhp[(size_t)r * Ek + c];
                uint2 vl = *(const uint2*)&vlp[(size_t)r * Ek + c];
                const __nv_bfloat16* ph = (const __nv_bfloat16*)&vh;
                const __nv_bfloat16* pl = (const __nv_bfloat16*)&vl;
                #pragma unroll
                for (int j = 0; j < 4; j++) {
                    VTh[(c + j) * 72 + r] = ph[j];
                    VTl[(c + j) * 72 + r] = pl[j];
                }
            }
        }
        __syncthreads();

        // ---- S = Q @ K^T (bf16x3) ----
        float s[8][4] = {};
        #pragma unroll
        for (int ks = 0; ks < 4; ks++) {
            int c0 = ks * 16 + 2 * tg;
            #pragma unroll
            for (int nt = 0; nt < 8; nt++) {
                int brow = nt * 8 + g;
                unsigned bhf[2] = { *(const unsigned*)&Kh[brow*72 + c0],
                                    *(const unsigned*)&Kh[brow*72 + c0 + 8] };
                unsigned blf[2] = { *(const unsigned*)&Kl[brow*72 + c0],
                                    *(const unsigned*)&Kl[brow*72 + c0 + 8] };
                mma16816(s[nt], qfh[ks], bhf);
                mma16816(s[nt], qfh[ks], blf);
                mma16816(s[nt], qfl[ks], bhf);
            }
        }

        // ---- mask + scale ----
        #pragma unroll
        for (int nt = 0; nt < 8; nt++) {
            int col = k0 + nt * 8 + 2 * tg;
            int2 m0 = *(const int2*)&mb[(size_t)qrow0 * Lk + col];
            int2 m1 = *(const int2*)&mb[(size_t)qrow1 * Lk + col];
            s[nt][0] = m0.x ? s[nt][0] * scale : -1e20f;
            s[nt][1] = m0.y ? s[nt][1] * scale : -1e20f;
            s[nt][2] = m1.x ? s[nt][2] * scale : -1e20f;
            s[nt][3] = m1.y ? s[nt][3] * scale : -1e20f;
        }

        // ---- online softmax (rows qrow0, qrow1) ----
        float mx0 = -1e30f, mx1 = -1e30f;
        #pragma unroll
        for (int nt = 0; nt < 8; nt++) {
            mx0 = fmaxf(mx0, fmaxf(s[nt][0], s[nt][1]));
            mx1 = fmaxf(mx1, fmaxf(s[nt][2], s[nt][3]));
        }
        mx0 = fmaxf(mx0, __shfl_xor_sync(0xffffffffu, mx0, 1));
        mx0 = fmaxf(mx0, __shfl_xor_sync(0xffffffffu, mx0, 2));
        mx1 = fmaxf(mx1, __shfl_xor_sync(0xffffffffu, mx1, 1));
        mx1 = fmaxf(mx1, __shfl_xor_sync(0xffffffffu, mx1, 2));

        float mn0 = fmaxf(mrun0, mx0), mn1 = fmaxf(mrun1, mx1);
        float a0 = __expf(mrun0 - mn0), a1 = __expf(mrun1 - mn1);
        mrun0 = mn0; mrun1 = mn1;

        float rs0 = 0.f, rs1 = 0.f;
        #pragma unroll
        for (int nt = 0; nt < 8; nt++) {
            s[nt][0] = __expf(s[nt][0] - mn0);
            s[nt][1] = __expf(s[nt][1] - mn0);
            s[nt][2] = __expf(s[nt][2] - mn1);
            s[nt][3] = __expf(s[nt][3] - mn1);
            rs0 += s[nt][0] + s[nt][1];
            rs1 += s[nt][2] + s[nt][3];
        }
        rs0 += __shfl_xor_sync(0xffffffffu, rs0, 1);
        rs0 += __shfl_xor_sync(0xffffffffu, rs0, 2);
        rs1 += __shfl_xor_sync(0xffffffffu, rs1, 1);
        rs1 += __shfl_xor_sync(0xffffffffu, rs1, 2);
        lrun0 = lrun0 * a0 + rs0;
        lrun1 = lrun1 * a1 + rs1;

        #pragma unroll
        for (int nt = 0; nt < 8; nt++) {
            O[nt][0] *= a0; O[nt][1] *= a0;
            O[nt][2] *= a1; O[nt][3] *= a1;
        }

        // ---- O += P @ V (P from registers, bf16x3) ----
        #pragma unroll
        for (int ks = 0; ks < 4; ks++) {
            unsigned aph[4], apl[4];
            pack_split(s[2*ks][0],   s[2*ks][1],   aph[0], apl[0]);
            pack_split(s[2*ks][2],   s[2*ks][3],   aph[1], apl[1]);
            pack_split(s[2*ks+1][0], s[2*ks+1][1], aph[2], apl[2]);
            pack_split(s[2*ks+1][2], s[2*ks+1][3], aph[3], apl[3]);
            int c0 = ks * 16 + 2 * tg;
            #pragma unroll
            for (int nt = 0; nt < 8; nt++) {
                int brow = nt * 8 + g;
                unsigned bhf[2] = { *(const unsigned*)&VTh[brow*72 + c0],
                                    *(const unsigned*)&VTh[brow*72 + c0 + 8] };
                unsigned blf[2] = { *(const unsigned*)&VTl[brow*72 + c0],
                                    *(const unsigned*)&VTl[brow*72 + c0 + 8] };
                mma16816(O[nt], aph, bhf);
                mma16816(O[nt], aph, blf);
                mma16816(O[nt], apl, bhf);
            }
        }
    }

    float inv0 = 1.0f / lrun0, inv1 = 1.0f / lrun1;
    size_t base0 = ((size_t)b * Lk + qrow0) * Ek + h * Dk;
    size_t base1 = ((size_t)b * Lk + qrow1) * Ek + h * Dk;
    #pragma unroll
    for (int nt = 0; nt < 8; nt++) {
        int col = nt * 8 + 2 * tg;
        unsigned hi, lo;
        pack_split(O[nt][0] * inv0, O[nt][1] * inv0, hi, lo);
        *(unsigned*)&g_oh[base0 + col] = hi;
        *(unsigned*)&g_ol[base0 + col] = lo;
        pack_split(O[nt][2] * inv1, O[nt][3] * inv1, hi, lo);
        *(unsigned*)&g_oh[base1 + col] = hi;
        *(unsigned*)&g_ol[base1 + col] = lo;
    }
}

// ---------------------------------------------------------------------------
// Output projection: out[m,n] = sum_k att[m,k] * Wo[n,k] + bo[n].
// Block 256 thr (8 warps), tile M=128 N=64, k-chunks of 32, bf16x3 mma.
// ---------------------------------------------------------------------------
__global__ __launch_bounds__(256) void outproj_kernel(const float* __restrict__ Wo,
                                                      const float* __restrict__ bo,
                                                      float* __restrict__ out) {
    __shared__ __nv_bfloat16 Ah[128*40], Al[128*40], Bh[64*40], Bl[64*40];

    int n0 = blockIdx.x * 64;
    int m0 = blockIdx.y * 128;
    int tid = threadIdx.x;
    int warp = tid >> 5, lane = tid & 31;
    int g = lane >> 2, tg = lane & 3;
    int mrow = warp * 16 + g;

    float acc[8][4] = {};

    for (int kc = 0; kc < Ek; kc += 32) {
        __syncthreads();
        #pragma unroll
        for (int i = 0; i < 4; i++) {
            int slot = tid + 256 * i;          // 1024 uint2 slots for 128x32
            int r = slot >> 3, c = (slot & 7) * 4;
            *(uint2*)&Ah[r*40 + c] = *(const uint2*)&g_oh[(size_t)(m0 + r) * Ek + kc + c];
            *(uint2*)&Al[r*40 + c] = *(const uint2*)&g_ol[(size_t)(m0 + r) * Ek + kc + c];
        }
        #pragma unroll
        for (int i = 0; i < 2; i++) {
            int slot = tid + 256 * i;          // 512 float4 slots for 64x32
            int r = slot >> 3, c = (slot & 7) * 4;
            float4 w = *(const float4*)&Wo[(size_t)(n0 + r) * Ek + kc + c];
            split1(w.x, Bh[r*40+c+0], Bl[r*40+c+0]);
            split1(w.y, Bh[r*40+c+1], Bl[r*40+c+1]);
            split1(w.z, Bh[r*40+c+2], Bl[r*40+c+2]);
            split1(w.w, Bh[r*40+c+3], Bl[r*40+c+3]);
        }
        __syncthreads();

        #pragma unroll
        for (int ks = 0; ks < 2; ks++) {
            int c0 = ks * 16 + 2 * tg;
            unsigned ahf[4] = { *(const unsigned*)&Ah[mrow*40 + c0],
                                *(const unsigned*)&Ah[(mrow+8)*40 + c0],
                                *(const unsigned*)&Ah[mrow*40 + c0 + 8],
                                *(const unsigned*)&Ah[(mrow+8)*40 + c0 + 8] };
            unsigned alf[4] = { *(const unsigned*)&Al[mrow*40 + c0],
                                *(const unsigned*)&Al[(mrow+8)*40 + c0],
                                *(const unsigned*)&Al[mrow*40 + c0 + 8],
                                *(const unsigned*)&Al[(mrow+8)*40 + c0 + 8] };
            #pragma unroll
            for (int nt = 0; nt < 8; nt++) {
                int brow = nt * 8 + g;
                unsigned bhf[2] = { *(const unsigned*)&Bh[brow*40 + c0],
                                    *(const unsigned*)&Bh[brow*40 + c0 + 8] };
                unsigned blf[2] = { *(const unsigned*)&Bl[brow*40 + c0],
                                    *(const unsigned*)&Bl[brow*40 + c0 + 8] };
                mma16816(acc[nt], ahf, bhf);
                mma16816(acc[nt], ahf, blf);
                mma16816(acc[nt], alf, bhf);
            }
        }
    }

    #pragma unroll
    for (int nt = 0; nt < 8; nt++) {
        int col = n0 + nt * 8 + 2 * tg;
        float2 bias = *(const float2*)&bo[col];
        float2 o0 = make_float2(acc[nt][0] + bias.x, acc[nt][1] + bias.y);
        float2 o1 = make_float2(acc[nt][2] + bias.x, acc[nt][3] + bias.y);
        *(float2*)&out[(size_t)(m0 + mrow) * Ek + col]     = o0;
        *(float2*)&out[(size_t)(m0 + mrow + 8) * Ek + col] = o1;
    }
}

// ---------------------------------------------------------------------------
extern "C" void kernel_launch(void* const* d_in, const int* in_sizes, int n_in,
                              void* d_out, int out_size) {
    const float* values = (const float*)d_in[0];
    const float* keys   = (const float*)d_in[1];
    const float* query  = (const float*)d_in[2];
    const int*   mask   = (const int*)d_in[3];
    // d_in[4] = size (scalar), compile-time constant here
    const float* Wv = (const float*)d_in[5];
    const float* Wk = (const float*)d_in[6];
    const float* Wq = (const float*)d_in[7];
    const float* Wo = (const float*)d_in[8];
    const float* bo = (const float*)d_in[9];
    float* out = (float*)d_out;

    static const int ATTN_SMEM = 6 * 64 * 72 * (int)sizeof(__nv_bfloat16);  // 55296
    cudaFuncSetAttribute(attn_kernel, cudaFuncAttributeMaxDynamicSharedMemorySize, ATTN_SMEM);

    dim3 pgrid(Lk / 64, Bk * Hk, 3);
    proj_kernel<<<pgrid, 128>>>(values, keys, query, Wv, Wk, Wq);

    dim3 agrid(Lk / 64, Bk * Hk);
    attn_kernel<<<agrid, 128, ATTN_SMEM>>>(mask);

    dim3 ogrid(Ek / 64, BLk / 128);
    outproj_kernel<<<ogrid, 256>>>(Wo, bo, out);
}

// round 11
// speedup vs baseline: 5.3781x; 1.2998x over previous
#include <cuda_runtime.h>
#include <cuda_bf16.h>

#define Bk 8
#define Lk 1024
#define Ek 1024
#define Hk 16
#define Dk 64
#define BLk (Bk*Lk)

// hi/lo bf16 scratch (device globals — no allocation in kernel_launch)
__device__ __nv_bfloat16 g_qh[(size_t)Bk*Lk*Ek], g_ql[(size_t)Bk*Lk*Ek];
__device__ __nv_bfloat16 g_kh[(size_t)Bk*Lk*Ek], g_kl[(size_t)Bk*Lk*Ek];
__device__ __nv_bfloat16 g_vh[(size_t)Bk*Lk*Ek], g_vl[(size_t)Bk*Lk*Ek];
__device__ __nv_bfloat16 g_oh[(size_t)Bk*Lk*Ek], g_ol[(size_t)Bk*Lk*Ek];

// ---------------------------------------------------------------------------
// mma.sync m16n8k16 row.col bf16 -> f32 accumulate
// ---------------------------------------------------------------------------
__device__ __forceinline__ void mma16816(float* d, const unsigned* a, const unsigned* b) {
    asm volatile(
        "mma.sync.aligned.m16n8k16.row.col.f32.bf16.bf16.f32 "
        "{%0,%1,%2,%3}, {%4,%5,%6,%7}, {%8,%9}, {%0,%1,%2,%3};\n"
        : "+f"(d[0]), "+f"(d[1]), "+f"(d[2]), "+f"(d[3])
        : "r"(a[0]), "r"(a[1]), "r"(a[2]), "r"(a[3]), "r"(b[0]), "r"(b[1]));
}

struct U4 { unsigned x, y, z, w; };

__device__ __forceinline__ U4 ldsm4(unsigned addr) {
    U4 r;
    asm volatile("ldmatrix.sync.aligned.m8n8.x4.shared.b16 {%0,%1,%2,%3}, [%4];\n"
                 : "=r"(r.x), "=r"(r.y), "=r"(r.z), "=r"(r.w) : "r"(addr));
    return r;
}
__device__ __forceinline__ U4 ldsm4t(unsigned addr) {
    U4 r;
    asm volatile("ldmatrix.sync.aligned.m8n8.x4.trans.shared.b16 {%0,%1,%2,%3}, [%4];\n"
                 : "=r"(r.x), "=r"(r.y), "=r"(r.z), "=r"(r.w) : "r"(addr));
    return r;
}
__device__ __forceinline__ unsigned smem_u32(const void* p) {
    return (unsigned)__cvta_generic_to_shared(p);
}

// per-lane byte offsets into a [rows][72] bf16 tile (144 B row stride)
// A-type x4 (m16k16 frag; also V-trans): matrices {r0..7|klo, r8..15|klo, r0..7|khi, r8..15|khi}
__device__ __forceinline__ unsigned lane_offA(int l) {
    return ((l & 7) + ((l >> 3) & 1) * 8) * 144u + ((l >> 4) & 1) * 16u;
}
// B-type x4 (two n8 tiles): matrices {n0|klo, n0|khi, n1|klo, n1|khi}
__device__ __forceinline__ unsigned lane_offB(int l) {
    return ((l & 7) + ((l >> 4) & 1) * 8) * 144u + ((l >> 3) & 1) * 16u;
}

__device__ __forceinline__ void split1(float x, __nv_bfloat16& h, __nv_bfloat16& l) {
    h = __float2bfloat16_rn(x);
    l = __float2bfloat16_rn(x - __bfloat162float(h));
}
__device__ __forceinline__ void pack_split(float x, float y, unsigned& hi, unsigned& lo) {
    __nv_bfloat162 h = __floats2bfloat162_rn(x, y);
    float rx = x - __bfloat162float(h.x);
    float ry = y - __bfloat162float(h.y);
    __nv_bfloat162 l = __floats2bfloat162_rn(rx, ry);
    hi = *(unsigned*)&h; lo = *(unsigned*)&l;
}

// ---------------------------------------------------------------------------
// Per-head projection: 128-row blocks, 8 warps, tile M=128 N=64 K=64.
// which = blockIdx.z: 0=q, 1=k, 2=v. Writes hi/lo bf16 pairs to global.
// ---------------------------------------------------------------------------
__global__ __launch_bounds__(256) void proj_kernel(const float* __restrict__ vin,
                                                   const float* __restrict__ kin,
                                                   const float* __restrict__ qin,
                                                   const float* __restrict__ Wv,
                                                   const float* __restrict__ Wk,
                                                   const float* __restrict__ Wq) {
    extern __shared__ __align__(16) char dsm[];
    __nv_bfloat16* Xh = (__nv_bfloat16*)dsm;            // 128*72
    __nv_bfloat16* Xl = Xh + 128 * 72;
    __nv_bfloat16* Wh = Xl + 128 * 72;                  // 64*72
    __nv_bfloat16* Wl = Wh + 64 * 72;

    int which = blockIdx.z;
    const float* in = (which == 0) ? qin : (which == 1) ? kin : vin;
    const float* W  = (which == 0) ? Wq  : (which == 1) ? Wk  : Wv;
    __nv_bfloat16* outh = (which == 0) ? g_qh : (which == 1) ? g_kh : g_vh;
    __nv_bfloat16* outl = (which == 0) ? g_ql : (which == 1) ? g_kl : g_vl;

    int bh = blockIdx.y;
    int b = bh >> 4, h = bh & 15;
    int l0 = blockIdx.x * 128;
    int tid = threadIdx.x;
    int warp = tid >> 5, lane = tid & 31;
    int g = lane >> 2, tg = lane & 3;

    const float* inp = in + ((size_t)b * Lk + l0) * Ek + h * Dk;
    const float* Wp  = W + (size_t)h * Dk * Dk;

    #pragma unroll
    for (int i = 0; i < 8; i++) {
        int slot = tid + 256 * i;            // 2048 float4 slots (128x64)
        int r = slot >> 4, c = (slot & 15) * 4;
        float4 x = *(const float4*)&inp[(size_t)r * Ek + c];
        split1(x.x, Xh[r*72+c+0], Xl[r*72+c+0]);
        split1(x.y, Xh[r*72+c+1], Xl[r*72+c+1]);
        split1(x.z, Xh[r*72+c+2], Xl[r*72+c+2]);
        split1(x.w, Xh[r*72+c+3], Xl[r*72+c+3]);
    }
    #pragma unroll
    for (int i = 0; i < 4; i++) {
        int slot = tid + 256 * i;            // 1024 float4 slots (64x64)
        int r = slot >> 4, c = (slot & 15) * 4;
        float4 w = *(const float4*)&Wp[r * 64 + c];
        split1(w.x, Wh[r*72+c+0], Wl[r*72+c+0]);
        split1(w.y, Wh[r*72+c+1], Wl[r*72+c+1]);
        split1(w.z, Wh[r*72+c+2], Wl[r*72+c+2]);
        split1(w.w, Wh[r*72+c+3], Wl[r*72+c+3]);
    }
    __syncthreads();

    int mrow = warp * 16;
    unsigned offA = lane_offA(lane), offB = lane_offB(lane);
    unsigned Xh_u = smem_u32(Xh) + mrow * 144 + offA;
    unsigned Xl_u = smem_u32(Xl) + mrow * 144 + offA;
    unsigned Wh_u = smem_u32(Wh) + offB;
    unsigned Wl_u = smem_u32(Wl) + offB;

    U4 ah[4], al[4];
    #pragma unroll
    for (int ks = 0; ks < 4; ks++) {
        ah[ks] = ldsm4(Xh_u + ks * 32);
        al[ks] = ldsm4(Xl_u + ks * 32);
    }

    float acc[8][4] = {};
    #pragma unroll
    for (int ks = 0; ks < 4; ks++) {
        #pragma unroll
        for (int ntp = 0; ntp < 4; ntp++) {
            U4 bh4 = ldsm4(Wh_u + ntp * 2304 + ks * 32);
            U4 bl4 = ldsm4(Wl_u + ntp * 2304 + ks * 32);
            unsigned b0h[2] = {bh4.x, bh4.y}, b1h[2] = {bh4.z, bh4.w};
            unsigned b0l[2] = {bl4.x, bl4.y}, b1l[2] = {bl4.z, bl4.w};
            mma16816(acc[2*ntp],   (unsigned*)&ah[ks], b0h);
            mma16816(acc[2*ntp],   (unsigned*)&ah[ks], b0l);
            mma16816(acc[2*ntp],   (unsigned*)&al[ks], b0h);
            mma16816(acc[2*ntp+1], (unsigned*)&ah[ks], b1h);
            mma16816(acc[2*ntp+1], (unsigned*)&ah[ks], b1l);
            mma16816(acc[2*ntp+1], (unsigned*)&al[ks], b1h);
        }
    }

    size_t base0 = ((size_t)b * Lk + l0 + mrow + g) * Ek + h * Dk;
    size_t base1 = base0 + (size_t)8 * Ek;
    #pragma unroll
    for (int nt = 0; nt < 8; nt++) {
        int col = nt * 8 + 2 * tg;
        unsigned hi, lo;
        pack_split(acc[nt][0], acc[nt][1], hi, lo);
        *(unsigned*)&outh[base0 + col] = hi;
        *(unsigned*)&outl[base0 + col] = lo;
        pack_split(acc[nt][2], acc[nt][3], hi, lo);
        *(unsigned*)&outh[base1 + col] = hi;
        *(unsigned*)&outl[base1 + col] = lo;
    }
}

// ---------------------------------------------------------------------------
// Flash attention: 512 thr (16 warps), q-tile 256 (m16/warp), k-tiles of 64.
// K/V hi/lo staged row-major; B-frags via ldmatrix (V via .trans). Q frags
// loaded once from global. P re-split hi/lo in registers -> A frags for P@V.
// ---------------------------------------------------------------------------
__global__ __launch_bounds__(512) void attn_kernel(const int* __restrict__ mask) {
    __shared__ __align__(16) __nv_bfloat16 Kh[64*72], Kl[64*72], Vh[64*72], Vl[64*72];

    int bh = blockIdx.y;
    int b = bh >> 4, h = bh & 15;
    int q0 = blockIdx.x * 256;
    int tid = threadIdx.x;
    int warp = tid >> 5, lane = tid & 31;
    int g = lane >> 2, tg = lane & 3;
    const float scale = 0.125f;

    int mrow = warp * 16;
    int qrow0 = q0 + mrow + g;
    int qrow1 = qrow0 + 8;

    // Q fragments directly from global (once per block)
    unsigned qfh[4][4], qfl[4][4];
    {
        size_t qb = ((size_t)b * Lk + qrow0) * Ek + h * Dk;
        #pragma unroll
        for (int ks = 0; ks < 4; ks++) {
            int c = ks * 16 + 2 * tg;
            qfh[ks][0] = *(const unsigned*)&g_qh[qb + c];
            qfh[ks][1] = *(const unsigned*)&g_qh[qb + 8 * Ek + c];
            qfh[ks][2] = *(const unsigned*)&g_qh[qb + c + 8];
            qfh[ks][3] = *(const unsigned*)&g_qh[qb + 8 * Ek + c + 8];
            qfl[ks][0] = *(const unsigned*)&g_ql[qb + c];
            qfl[ks][1] = *(const unsigned*)&g_ql[qb + 8 * Ek + c];
            qfl[ks][2] = *(const unsigned*)&g_ql[qb + c + 8];
            qfl[ks][3] = *(const unsigned*)&g_ql[qb + 8 * Ek + c + 8];
        }
    }

    unsigned offA = lane_offA(lane), offB = lane_offB(lane);
    unsigned Kh_u = smem_u32(Kh) + offB;
    unsigned Kl_u = smem_u32(Kl) + offB;
    unsigned Vh_u = smem_u32(Vh) + offA;
    unsigned Vl_u = smem_u32(Vl) + offA;

    float mrun0 = -1e30f, mrun1 = -1e30f, lrun0 = 0.f, lrun1 = 0.f;
    float O[8][4] = {};
    const int* mb = mask + (size_t)b * Lk * Lk;

    for (int kt = 0; kt < Lk / 64; kt++) {
        int k0 = kt * 64;
        __syncthreads();
        {
            size_t gb = ((size_t)b * Lk + k0) * Ek + h * Dk;
            #pragma unroll
            for (int i = 0; i < 2; i++) {
                int slot = tid + 512 * i;        // 1024 uint2 slots per array
                int r = slot >> 4, c = (slot & 15) * 4;
                size_t go = gb + (size_t)r * Ek + c;
                *(uint2*)&Kh[r*72 + c] = *(const uint2*)&g_kh[go];
                *(uint2*)&Kl[r*72 + c] = *(const uint2*)&g_kl[go];
                *(uint2*)&Vh[r*72 + c] = *(const uint2*)&g_vh[go];
                *(uint2*)&Vl[r*72 + c] = *(const uint2*)&g_vl[go];
            }
        }
        __syncthreads();

        // ---- S = Q @ K^T (bf16x3) ----
        float s[8][4] = {};
        #pragma unroll
        for (int ks = 0; ks < 4; ks++) {
            #pragma unroll
            for (int ntp = 0; ntp < 4; ntp++) {
                U4 bh4 = ldsm4(Kh_u + ntp * 2304 + ks * 32);
                U4 bl4 = ldsm4(Kl_u + ntp * 2304 + ks * 32);
                unsigned b0h[2] = {bh4.x, bh4.y}, b1h[2] = {bh4.z, bh4.w};
                unsigned b0l[2] = {bl4.x, bl4.y}, b1l[2] = {bl4.z, bl4.w};
                mma16816(s[2*ntp],   qfh[ks], b0h);
                mma16816(s[2*ntp],   qfh[ks], b0l);
                mma16816(s[2*ntp],   qfl[ks], b0h);
                mma16816(s[2*ntp+1], qfh[ks], b1h);
                mma16816(s[2*ntp+1], qfh[ks], b1l);
                mma16816(s[2*ntp+1], qfl[ks], b1h);
            }
        }

        // ---- mask + scale ----
        #pragma unroll
        for (int nt = 0; nt < 8; nt++) {
            int col = k0 + nt * 8 + 2 * tg;
            int2 m0 = *(const int2*)&mb[(size_t)qrow0 * Lk + col];
            int2 m1 = *(const int2*)&mb[(size_t)qrow1 * Lk + col];
            s[nt][0] = m0.x ? s[nt][0] * scale : -1e20f;
            s[nt][1] = m0.y ? s[nt][1] * scale : -1e20f;
            s[nt][2] = m1.x ? s[nt][2] * scale : -1e20f;
            s[nt][3] = m1.y ? s[nt][3] * scale : -1e20f;
        }

        // ---- online softmax ----
        float mx0 = -1e30f, mx1 = -1e30f;
        #pragma unroll
        for (int nt = 0; nt < 8; nt++) {
            mx0 = fmaxf(mx0, fmaxf(s[nt][0], s[nt][1]));
            mx1 = fmaxf(mx1, fmaxf(s[nt][2], s[nt][3]));
        }
        mx0 = fmaxf(mx0, __shfl_xor_sync(0xffffffffu, mx0, 1));
        mx0 = fmaxf(mx0, __shfl_xor_sync(0xffffffffu, mx0, 2));
        mx1 = fmaxf(mx1, __shfl_xor_sync(0xffffffffu, mx1, 1));
        mx1 = fmaxf(mx1, __shfl_xor_sync(0xffffffffu, mx1, 2));

        float mn0 = fmaxf(mrun0, mx0), mn1 = fmaxf(mrun1, mx1);
        float a0 = __expf(mrun0 - mn0), a1 = __expf(mrun1 - mn1);
        mrun0 = mn0; mrun1 = mn1;

        float rs0 = 0.f, rs1 = 0.f;
        #pragma unroll
        for (int nt = 0; nt < 8; nt++) {
            s[nt][0] = __expf(s[nt][0] - mn0);
            s[nt][1] = __expf(s[nt][1] - mn0);
            s[nt][2] = __expf(s[nt][2] - mn1);
            s[nt][3] = __expf(s[nt][3] - mn1);
            rs0 += s[nt][0] + s[nt][1];
            rs1 += s[nt][2] + s[nt][3];
        }
        rs0 += __shfl_xor_sync(0xffffffffu, rs0, 1);
        rs0 += __shfl_xor_sync(0xffffffffu, rs0, 2);
        rs1 += __shfl_xor_sync(0xffffffffu, rs1, 1);
        rs1 += __shfl_xor_sync(0xffffffffu, rs1, 2);
        lrun0 = lrun0 * a0 + rs0;
        lrun1 = lrun1 * a1 + rs1;

        #pragma unroll
        for (int nt = 0; nt < 8; nt++) {
            O[nt][0] *= a0; O[nt][1] *= a0;
            O[nt][2] *= a1; O[nt][3] *= a1;
        }

        // ---- O += P @ V (P from registers, V via ldmatrix.trans, bf16x3) ----
        #pragma unroll
        for (int ks = 0; ks < 4; ks++) {
            unsigned aph[4], apl[4];
            pack_split(s[2*ks][0],   s[2*ks][1],   aph[0], apl[0]);
            pack_split(s[2*ks][2],   s[2*ks][3],   aph[1], apl[1]);
            pack_split(s[2*ks+1][0], s[2*ks+1][1], aph[2], apl[2]);
            pack_split(s[2*ks+1][2], s[2*ks+1][3], aph[3], apl[3]);
            #pragma unroll
            for (int ntp = 0; ntp < 4; ntp++) {
                U4 vh4 = ldsm4t(Vh_u + ks * 2304 + ntp * 32);
                U4 vl4 = ldsm4t(Vl_u + ks * 2304 + ntp * 32);
                unsigned b0h[2] = {vh4.x, vh4.y}, b1h[2] = {vh4.z, vh4.w};
                unsigned b0l[2] = {vl4.x, vl4.y}, b1l[2] = {vl4.z, vl4.w};
                mma16816(O[2*ntp],   aph, b0h);
                mma16816(O[2*ntp],   aph, b0l);
                mma16816(O[2*ntp],   apl, b0h);
                mma16816(O[2*ntp+1], aph, b1h);
                mma16816(O[2*ntp+1], aph, b1l);
                mma16816(O[2*ntp+1], apl, b1h);
            }
        }
    }

    float inv0 = 1.0f / lrun0, inv1 = 1.0f / lrun1;
    size_t base0 = ((size_t)b * Lk + qrow0) * Ek + h * Dk;
    size_t base1 = ((size_t)b * Lk + qrow1) * Ek + h * Dk;
    #pragma unroll
    for (int nt = 0; nt < 8; nt++) {
        int col = nt * 8 + 2 * tg;
        unsigned hi, lo;
        pack_split(O[nt][0] * inv0, O[nt][1] * inv0, hi, lo);
        *(unsigned*)&g_oh[base0 + col] = hi;
        *(unsigned*)&g_ol[base0 + col] = lo;
        pack_split(O[nt][2] * inv1, O[nt][3] * inv1, hi, lo);
        *(unsigned*)&g_oh[base1 + col] = hi;
        *(unsigned*)&g_ol[base1 + col] = lo;
    }
}

// ---------------------------------------------------------------------------
// Output projection: out[m,n] = sum_k att[m,k] * Wo[n,k] + bo[n].
// 256 thr (8 warps), tile M=128 N=64, k-chunks of 64, ldmatrix-fed bf16x3.
// ---------------------------------------------------------------------------
__global__ __launch_bounds__(256) void outproj_kernel(const float* __restrict__ Wo,
                                                      const float* __restrict__ bo,
                                                      float* __restrict__ out) {
    extern __shared__ __align__(16) char dsm[];
    __nv_bfloat16* Ah = (__nv_bfloat16*)dsm;            // 128*72
    __nv_bfloat16* Al = Ah + 128 * 72;
    __nv_bfloat16* Bh = Al + 128 * 72;                  // 64*72
    __nv_bfloat16* Bl = Bh + 64 * 72;

    int n0 = blockIdx.x * 64;
    int m0 = blockIdx.y * 128;
    int tid = threadIdx.x;
    int warp = tid >> 5, lane = tid & 31;
    int g = lane >> 2, tg = lane & 3;
    int mrow = warp * 16;

    unsigned offA = lane_offA(lane), offB = lane_offB(lane);
    unsigned Ah_u = smem_u32(Ah) + mrow * 144 + offA;
    unsigned Al_u = smem_u32(Al) + mrow * 144 + offA;
    unsigned Bh_u = smem_u32(Bh) + offB;
    unsigned Bl_u = smem_u32(Bl) + offB;

    float acc[8][4] = {};

    for (int kc = 0; kc < Ek; kc += 64) {
        __syncthreads();
        #pragma unroll
        for (int i = 0; i < 8; i++) {
            int slot = tid + 256 * i;          // 2048 uint2 slots (128x64)
            int r = slot >> 4, c = (slot & 15) * 4;
            size_t go = (size_t)(m0 + r) * Ek + kc + c;
            *(uint2*)&Ah[r*72 + c] = *(const uint2*)&g_oh[go];
            *(uint2*)&Al[r*72 + c] = *(const uint2*)&g_ol[go];
        }
        #pragma unroll
        for (int i = 0; i < 4; i++) {
            int slot = tid + 256 * i;          // 1024 float4 slots (64x64)
            int r = slot >> 4, c = (slot & 15) * 4;
            float4 w = *(const float4*)&Wo[(size_t)(n0 + r) * Ek + kc + c];
            split1(w.x, Bh[r*72+c+0], Bl[r*72+c+0]);
            split1(w.y, Bh[r*72+c+1], Bl[r*72+c+1]);
            split1(w.z, Bh[r*72+c+2], Bl[r*72+c+2]);
            split1(w.w, Bh[r*72+c+3], Bl[r*72+c+3]);
        }
        __syncthreads();

        #pragma unroll
        for (int ks = 0; ks < 4; ks++) {
            U4 ah4 = ldsm4(Ah_u + ks * 32);
            U4 al4 = ldsm4(Al_u + ks * 32);
            #pragma unroll
            for (int ntp = 0; ntp < 4; ntp++) {
                U4 bh4 = ldsm4(Bh_u + ntp * 2304 + ks * 32);
                U4 bl4 = ldsm4(Bl_u + ntp * 2304 + ks * 32);
                unsigned b0h[2] = {bh4.x, bh4.y}, b1h[2] = {bh4.z, bh4.w};
                unsigned b0l[2] = {bl4.x, bl4.y}, b1l[2] = {bl4.z, bl4.w};
                mma16816(acc[2*ntp],   (unsigned*)&ah4, b0h);
                mma16816(acc[2*ntp],   (unsigned*)&ah4, b0l);
                mma16816(acc[2*ntp],   (unsigned*)&al4, b0h);
                mma16816(acc[2*ntp+1], (unsigned*)&ah4, b1h);
                mma16816(acc[2*ntp+1], (unsigned*)&ah4, b1l);
                mma16816(acc[2*ntp+1], (unsigned*)&al4, b1h);
            }
        }
    }

    #pragma unroll
    for (int nt = 0; nt < 8; nt++) {
        int col = n0 + nt * 8 + 2 * tg;
        float2 bias = *(const float2*)&bo[col];
        float2 o0 = make_float2(acc[nt][0] + bias.x, acc[nt][1] + bias.y);
        float2 o1 = make_float2(acc[nt][2] + bias.x, acc[nt][3] + bias.y);
        *(float2*)&out[(size_t)(m0 + mrow + g) * Ek + col]     = o0;
        *(float2*)&out[(size_t)(m0 + mrow + g + 8) * Ek + col] = o1;
    }
}

// ---------------------------------------------------------------------------
extern "C" void kernel_launch(void* const* d_in, const int* in_sizes, int n_in,
                              void* d_out, int out_size) {
    const float* values = (const float*)d_in[0];
    const float* keys   = (const float*)d_in[1];
    const float* query  = (const float*)d_in[2];
    const int*   mask   = (const int*)d_in[3];
    // d_in[4] = size (scalar), compile-time constant here
    const float* Wv = (const float*)d_in[5];
    const float* Wk = (const float*)d_in[6];
    const float* Wq = (const float*)d_in[7];
    const float* Wo = (const float*)d_in[8];
    const float* bo = (const float*)d_in[9];
    float* out = (float*)d_out;

    static const int GEMM_SMEM = (128 * 72 * 2 + 64 * 72 * 2) * (int)sizeof(__nv_bfloat16); // 55296
    cudaFuncSetAttribute(proj_kernel,    cudaFuncAttributeMaxDynamicSharedMemorySize, GEMM_SMEM);
    cudaFuncSetAttribute(outproj_kernel, cudaFuncAttributeMaxDynamicSharedMemorySize, GEMM_SMEM);

    dim3 pgrid(Lk / 128, Bk * Hk, 3);
    proj_kernel<<<pgrid, 256, GEMM_SMEM>>>(values, keys, query, Wv, Wk, Wq);

    dim3 agrid(Lk / 256, Bk * Hk);
    attn_kernel<<<agrid, 512>>>(mask);

    dim3 ogrid(Ek / 64, BLk / 128);
    outproj_kernel<<<ogrid, 256, GEMM_SMEM>>>(Wo, bo, out);
}

// round 15
// speedup vs baseline: 5.5203x; 1.0264x over previous
#include <cuda_runtime.h>
#include <cuda_bf16.h>

#define Bk 8
#define Lk 1024
#define Ek 1024
#define Hk 16
#define Dk 64
#define BLk (Bk*Lk)

// hi/lo bf16 scratch (device globals — no allocation in kernel_launch)
__device__ __nv_bfloat16 g_qh[(size_t)Bk*Lk*Ek], g_ql[(size_t)Bk*Lk*Ek];
__device__ __nv_bfloat16 g_kh[(size_t)Bk*Lk*Ek], g_kl[(size_t)Bk*Lk*Ek];
__device__ __nv_bfloat16 g_vh[(size_t)Bk*Lk*Ek], g_vl[(size_t)Bk*Lk*Ek];
__device__ __nv_bfloat16 g_oh[(size_t)Bk*Lk*Ek], g_ol[(size_t)Bk*Lk*Ek];
__device__ __nv_bfloat16 g_woh[(size_t)Ek*Ek],   g_wol[(size_t)Ek*Ek];

// ---------------------------------------------------------------------------
__device__ __forceinline__ void mma16816(float* d, const unsigned* a, const unsigned* b) {
    asm volatile(
        "mma.sync.aligned.m16n8k16.row.col.f32.bf16.bf16.f32 "
        "{%0,%1,%2,%3}, {%4,%5,%6,%7}, {%8,%9}, {%0,%1,%2,%3};\n"
        : "+f"(d[0]), "+f"(d[1]), "+f"(d[2]), "+f"(d[3])
        : "r"(a[0]), "r"(a[1]), "r"(a[2]), "r"(a[3]), "r"(b[0]), "r"(b[1]));
}

struct U4 { unsigned x, y, z, w; };

__device__ __forceinline__ U4 ldsm4(unsigned addr) {
    U4 r;
    asm volatile("ldmatrix.sync.aligned.m8n8.x4.shared.b16 {%0,%1,%2,%3}, [%4];\n"
                 : "=r"(r.x), "=r"(r.y), "=r"(r.z), "=r"(r.w) : "r"(addr));
    return r;
}
__device__ __forceinline__ U4 ldsm4t(unsigned addr) {
    U4 r;
    asm volatile("ldmatrix.sync.aligned.m8n8.x4.trans.shared.b16 {%0,%1,%2,%3}, [%4];\n"
                 : "=r"(r.x), "=r"(r.y), "=r"(r.z), "=r"(r.w) : "r"(addr));
    return r;
}
__device__ __forceinline__ unsigned smem_u32(const void* p) {
    return (unsigned)__cvta_generic_to_shared(p);
}
__device__ __forceinline__ void cp16(unsigned smem_dst, const void* gsrc) {
    asm volatile("cp.async.cg.shared.global [%0], [%1], 16;\n" :: "r"(smem_dst), "l"(gsrc));
}
__device__ __forceinline__ void cp_commit() { asm volatile("cp.async.commit_group;\n"); }
template <int N> __device__ __forceinline__ void cp_wait() {
    asm volatile("cp.async.wait_group %0;\n" :: "n"(N));
}

// per-lane byte offsets into a tile with given row stride (bytes)
__device__ __forceinline__ unsigned lane_offA(int l, int strideB) {
    return ((l & 7) + ((l >> 3) & 1) * 8) * (unsigned)strideB + ((l >> 4) & 1) * 16u;
}
__device__ __forceinline__ unsigned lane_offB(int l, int strideB) {
    return ((l & 7) + ((l >> 4) & 1) * 8) * (unsigned)strideB + ((l >> 3) & 1) * 16u;
}

__device__ __forceinline__ void split1(float x, __nv_bfloat16& h, __nv_bfloat16& l) {
    h = __float2bfloat16_rn(x);
    l = __float2bfloat16_rn(x - __bfloat162float(h));
}
__device__ __forceinline__ void pack_split(float x, float y, unsigned& hi, unsigned& lo) {
    __nv_bfloat162 h = __floats2bfloat162_rn(x, y);
    float rx = x - __bfloat162float(h.x);
    float ry = y - __bfloat162float(h.y);
    __nv_bfloat162 l = __floats2bfloat162_rn(rx, ry);
    hi = *(unsigned*)&h; lo = *(unsigned*)&l;
}

// ---------------------------------------------------------------------------
// Pre-split Wo (fp32 -> hi/lo bf16), once per launch. 1M elems.
// ---------------------------------------------------------------------------
__global__ __launch_bounds__(256) void split_wo_kernel(const float* __restrict__ Wo) {
    int slot = blockIdx.x * 256 + threadIdx.x;     // float4 slot
    float4 w = *(const float4*)&Wo[(size_t)slot * 4];
    __nv_bfloat16 h0, l0, h1, l1, h2, l2, h3, l3;
    split1(w.x, h0, l0); split1(w.y, h1, l1);
    split1(w.z, h2, l2); split1(w.w, h3, l3);
    __nv_bfloat16 hv[4] = {h0, h1, h2, h3}, lv[4] = {l0, l1, l2, l3};
    *(uint2*)&g_woh[(size_t)slot * 4] = *(uint2*)hv;
    *(uint2*)&g_wol[(size_t)slot * 4] = *(uint2*)lv;
}

// ---------------------------------------------------------------------------
// Per-head projection: 128-row blocks, 8 warps, tile M=128 N=64 K=64.
// which = blockIdx.z: 0=q, 1=k, 2=v. Writes hi/lo bf16 pairs to global.
// ---------------------------------------------------------------------------
__global__ __launch_bounds__(256) void proj_kernel(const float* __restrict__ vin,
                                                   const float* __restrict__ kin,
                                                   const float* __restrict__ qin,
                                                   const float* __restrict__ Wv,
                                                   const float* __restrict__ Wk,
                                                   const float* __restrict__ Wq) {
    extern __shared__ __align__(16) char dsm[];
    __nv_bfloat16* Xh = (__nv_bfloat16*)dsm;            // 128*72
    __nv_bfloat16* Xl = Xh + 128 * 72;
    __nv_bfloat16* Wh = Xl + 128 * 72;                  // 64*72
    __nv_bfloat16* Wl = Wh + 64 * 72;

    int which = blockIdx.z;
    const float* in = (which == 0) ? qin : (which == 1) ? kin : vin;
    const float* W  = (which == 0) ? Wq  : (which == 1) ? Wk  : Wv;
    __nv_bfloat16* outh = (which == 0) ? g_qh : (which == 1) ? g_kh : g_vh;
    __nv_bfloat16* outl = (which == 0) ? g_ql : (which == 1) ? g_kl : g_vl;

    int bh = blockIdx.y;
    int b = bh >> 4, h = bh & 15;
    int l0 = blockIdx.x * 128;
    int tid = threadIdx.x;
    int warp = tid >> 5, lane = tid & 31;
    int g = lane >> 2, tg = lane & 3;

    const float* inp = in + ((size_t)b * Lk + l0) * Ek + h * Dk;
    const float* Wp  = W + (size_t)h * Dk * Dk;

    #pragma unroll
    for (int i = 0; i < 8; i++) {
        int slot = tid + 256 * i;            // 2048 float4 slots (128x64)
        int r = slot >> 4, c = (slot & 15) * 4;
        float4 x = *(const float4*)&inp[(size_t)r * Ek + c];
        split1(x.x, Xh[r*72+c+0], Xl[r*72+c+0]);
        split1(x.y, Xh[r*72+c+1], Xl[r*72+c+1]);
        split1(x.z, Xh[r*72+c+2], Xl[r*72+c+2]);
        split1(x.w, Xh[r*72+c+3], Xl[r*72+c+3]);
    }
    #pragma unroll
    for (int i = 0; i < 4; i++) {
        int slot = tid + 256 * i;            // 1024 float4 slots (64x64)
        int r = slot >> 4, c = (slot & 15) * 4;
        float4 w = *(const float4*)&Wp[r * 64 + c];
        split1(w.x, Wh[r*72+c+0], Wl[r*72+c+0]);
        split1(w.y, Wh[r*72+c+1], Wl[r*72+c+1]);
        split1(w.z, Wh[r*72+c+2], Wl[r*72+c+2]);
        split1(w.w, Wh[r*72+c+3], Wl[r*72+c+3]);
    }
    __syncthreads();

    int mrow = warp * 16;
    unsigned offA = lane_offA(lane, 144), offB = lane_offB(lane, 144);
    unsigned Xh_u = smem_u32(Xh) + mrow * 144 + offA;
    unsigned Xl_u = smem_u32(Xl) + mrow * 144 + offA;
    unsigned Wh_u = smem_u32(Wh) + offB;
    unsigned Wl_u = smem_u32(Wl) + offB;

    U4 ah[4], al[4];
    #pragma unroll
    for (int ks = 0; ks < 4; ks++) {
        ah[ks] = ldsm4(Xh_u + ks * 32);
        al[ks] = ldsm4(Xl_u + ks * 32);
    }

    float acc[8][4] = {};
    #pragma unroll
    for (int ks = 0; ks < 4; ks++) {
        #pragma unroll
        for (int ntp = 0; ntp < 4; ntp++) {
            U4 bh4 = ldsm4(Wh_u + ntp * 2304 + ks * 32);
            U4 bl4 = ldsm4(Wl_u + ntp * 2304 + ks * 32);
            unsigned b0h[2] = {bh4.x, bh4.y}, b1h[2] = {bh4.z, bh4.w};
            unsigned b0l[2] = {bl4.x, bl4.y}, b1l[2] = {bl4.z, bl4.w};
            mma16816(acc[2*ntp],   (unsigned*)&ah[ks], b0h);
            mma16816(acc[2*ntp],   (unsigned*)&ah[ks], b0l);
            mma16816(acc[2*ntp],   (unsigned*)&al[ks], b0h);
            mma16816(acc[2*ntp+1], (unsigned*)&ah[ks], b1h);
            mma16816(acc[2*ntp+1], (unsigned*)&ah[ks], b1l);
            mma16816(acc[2*ntp+1], (unsigned*)&al[ks], b1h);
        }
    }

    size_t base0 = ((size_t)b * Lk + l0 + mrow + g) * Ek + h * Dk;
    size_t base1 = base0 + (size_t)8 * Ek;
    #pragma unroll
    for (int nt = 0; nt < 8; nt++) {
        int col = nt * 8 + 2 * tg;
        unsigned hi, lo;
        pack_split(acc[nt][0], acc[nt][1], hi, lo);
        *(unsigned*)&outh[base0 + col] = hi;
        *(unsigned*)&outl[base0 + col] = lo;
        pack_split(acc[nt][2], acc[nt][3], hi, lo);
        *(unsigned*)&outh[base1 + col] = hi;
        *(unsigned*)&outl[base1 + col] = lo;
    }
}

// ---------------------------------------------------------------------------
// Flash attention: 512 thr (16 warps), q-tile 256 (m16/warp), k-tiles of 64.
// 2-stage cp.async ping-pong for K/V hi/lo tiles. Q frags from global once.
// P re-split hi/lo in registers -> A frags for P@V (V via ldmatrix.trans).
// ---------------------------------------------------------------------------
#define AT_STAGE_B 36864   // 4 arrays * 64*72*2 bytes
#define AT_ARR_B   9216    // 64*72*2 bytes

__global__ __launch_bounds__(512) void attn_kernel(const int* __restrict__ mask) {
    extern __shared__ __align__(16) char dsm[];
    __nv_bfloat16* smb = (__nv_bfloat16*)dsm;
    unsigned sbase = smem_u32(smb);

    int bh = blockIdx.y;
    int b = bh >> 4, h = bh & 15;
    int q0 = blockIdx.x * 256;
    int tid = threadIdx.x;
    int warp = tid >> 5, lane = tid & 31;
    int g = lane >> 2, tg = lane & 3;
    const float scale = 0.125f;

    int mrow = warp * 16;
    int qrow0 = q0 + mrow + g;
    int qrow1 = qrow0 + 8;

    // Q fragments directly from global (once per block)
    unsigned qfh[4][4], qfl[4][4];
    {
        size_t qb = ((size_t)b * Lk + qrow0) * Ek + h * Dk;
        #pragma unroll
        for (int ks = 0; ks < 4; ks++) {
            int c = ks * 16 + 2 * tg;
            qfh[ks][0] = *(const unsigned*)&g_qh[qb + c];
            qfh[ks][1] = *(const unsigned*)&g_qh[qb + 8 * Ek + c];
            qfh[ks][2] = *(const unsigned*)&g_qh[qb + c + 8];
            qfh[ks][3] = *(const unsigned*)&g_qh[qb + 8 * Ek + c + 8];
            qfl[ks][0] = *(const unsigned*)&g_ql[qb + c];
            qfl[ks][1] = *(const unsigned*)&g_ql[qb + 8 * Ek + c];
            qfl[ks][2] = *(const unsigned*)&g_ql[qb + c + 8];
            qfl[ks][3] = *(const unsigned*)&g_ql[qb + 8 * Ek + c + 8];
        }
    }

    unsigned offA = lane_offA(lane, 144), offB = lane_offB(lane, 144);

    float mrun0 = -1e30f, mrun1 = -1e30f, lrun0 = 0.f, lrun1 = 0.f;
    float O[8][4] = {};
    const int* mb = mask + (size_t)b * Lk * Lk;

    // cp.async issue of tile kt into stage s: 4 chunks of 16B per thread
    const __nv_bfloat16* srcs[4] = {g_kh, g_kl, g_vh, g_vl};
    int ld_r = tid >> 3;                 // 0..63
    int ld_c = (tid & 7) * 8;            // element col (8 bf16 = 16 B)
    unsigned ld_dst = sbase + (unsigned)(ld_r * 144 + ld_c * 2);

    // prologue: stage 0
    {
        size_t gb = ((size_t)b * Lk + 0) * Ek + h * Dk + (size_t)ld_r * Ek + ld_c;
        #pragma unroll
        for (int i = 0; i < 4; i++)
            cp16(ld_dst + i * AT_ARR_B, srcs[i] + gb);
        cp_commit();
    }

    for (int kt = 0; kt < Lk / 64; kt++) {
        int s = kt & 1;
        if (kt + 1 < Lk / 64) {
            size_t gb = ((size_t)b * Lk + (kt + 1) * 64) * Ek + h * Dk + (size_t)ld_r * Ek + ld_c;
            unsigned dst = ld_dst + (1 - s) * AT_STAGE_B;
            #pragma unroll
            for (int i = 0; i < 4; i++)
                cp16(dst + i * AT_ARR_B, srcs[i] + gb);
            cp_commit();
            cp_wait<1>();
        } else {
            cp_wait<0>();
        }
        __syncthreads();

        unsigned Kh_u = sbase + s * AT_STAGE_B + offB;
        unsigned Kl_u = Kh_u + AT_ARR_B;
        unsigned Vh_u = sbase + s * AT_STAGE_B + 2 * AT_ARR_B + offA;
        unsigned Vl_u = Vh_u + AT_ARR_B;
        int k0 = kt * 64;

        // ---- S = Q @ K^T (bf16x3) ----
        float sc[8][4] = {};
        #pragma unroll
        for (int ks = 0; ks < 4; ks++) {
            #pragma unroll
            for (int ntp = 0; ntp < 4; ntp++) {
                U4 bh4 = ldsm4(Kh_u + ntp * 2304 + ks * 32);
                U4 bl4 = ldsm4(Kl_u + ntp * 2304 + ks * 32);
                unsigned b0h[2] = {bh4.x, bh4.y}, b1h[2] = {bh4.z, bh4.w};
                unsigned b0l[2] = {bl4.x, bl4.y}, b1l[2] = {bl4.z, bl4.w};
                mma16816(sc[2*ntp],   qfh[ks], b0h);
                mma16816(sc[2*ntp],   qfh[ks], b0l);
                mma16816(sc[2*ntp],   qfl[ks], b0h);
                mma16816(sc[2*ntp+1], qfh[ks], b1h);
                mma16816(sc[2*ntp+1], qfh[ks], b1l);
                mma16816(sc[2*ntp+1], qfl[ks], b1h);
            }
        }

        // ---- mask + scale ----
        #pragma unroll
        for (int nt = 0; nt < 8; nt++) {
            int col = k0 + nt * 8 + 2 * tg;
            int2 m0 = *(const int2*)&mb[(size_t)qrow0 * Lk + col];
            int2 m1 = *(const int2*)&mb[(size_t)qrow1 * Lk + col];
            sc[nt][0] = m0.x ? sc[nt][0] * scale : -1e20f;
            sc[nt][1] = m0.y ? sc[nt][1] * scale : -1e20f;
            sc[nt][2] = m1.x ? sc[nt][2] * scale : -1e20f;
            sc[nt][3] = m1.y ? sc[nt][3] * scale : -1e20f;
        }

        // ---- online softmax ----
        float mx0 = -1e30f, mx1 = -1e30f;
        #pragma unroll
        for (int nt = 0; nt < 8; nt++) {
            mx0 = fmaxf(mx0, fmaxf(sc[nt][0], sc[nt][1]));
            mx1 = fmaxf(mx1, fmaxf(sc[nt][2], sc[nt][3]));
        }
        mx0 = fmaxf(mx0, __shfl_xor_sync(0xffffffffu, mx0, 1));
        mx0 = fmaxf(mx0, __shfl_xor_sync(0xffffffffu, mx0, 2));
        mx1 = fmaxf(mx1, __shfl_xor_sync(0xffffffffu, mx1, 1));
        mx1 = fmaxf(mx1, __shfl_xor_sync(0xffffffffu, mx1, 2));

        float mn0 = fmaxf(mrun0, mx0), mn1 = fmaxf(mrun1, mx1);
        float a0 = __expf(mrun0 - mn0), a1 = __expf(mrun1 - mn1);
        mrun0 = mn0; mrun1 = mn1;

        float rs0 = 0.f, rs1 = 0.f;
        #pragma unroll
        for (int nt = 0; nt < 8; nt++) {
            sc[nt][0] = __expf(sc[nt][0] - mn0);
            sc[nt][1] = __expf(sc[nt][1] - mn0);
            sc[nt][2] = __expf(sc[nt][2] - mn1);
            sc[nt][3] = __expf(sc[nt][3] - mn1);
            rs0 += sc[nt][0] + sc[nt][1];
            rs1 += sc[nt][2] + sc[nt][3];
        }
        rs0 += __shfl_xor_sync(0xffffffffu, rs0, 1);
        rs0 += __shfl_xor_sync(0xffffffffu, rs0, 2);
        rs1 += __shfl_xor_sync(0xffffffffu, rs1, 1);
        rs1 += __shfl_xor_sync(0xffffffffu, rs1, 2);
        lrun0 = lrun0 * a0 + rs0;
        lrun1 = lrun1 * a1 + rs1;

        #pragma unroll
        for (int nt = 0; nt < 8; nt++) {
            O[nt][0] *= a0; O[nt][1] *= a0;
            O[nt][2] *= a1; O[nt][3] *= a1;
        }

        // ---- O += P @ V ----
        #pragma unroll
        for (int ks = 0; ks < 4; ks++) {
            unsigned aph[4], apl[4];
            pack_split(sc[2*ks][0],   sc[2*ks][1],   aph[0], apl[0]);
            pack_split(sc[2*ks][2],   sc[2*ks][3],   aph[1], apl[1]);
            pack_split(sc[2*ks+1][0], sc[2*ks+1][1], aph[2], apl[2]);
            pack_split(sc[2*ks+1][2], sc[2*ks+1][3], aph[3], apl[3]);
            #pragma unroll
            for (int ntp = 0; ntp < 4; ntp++) {
                U4 vh4 = ldsm4t(Vh_u + ks * 2304 + ntp * 32);
                U4 vl4 = ldsm4t(Vl_u + ks * 2304 + ntp * 32);
                unsigned b0h[2] = {vh4.x, vh4.y}, b1h[2] = {vh4.z, vh4.w};
                unsigned b0l[2] = {vl4.x, vl4.y}, b1l[2] = {vl4.z, vl4.w};
                mma16816(O[2*ntp],   aph, b0h);
                mma16816(O[2*ntp],   aph, b0l);
                mma16816(O[2*ntp],   apl, b0h);
                mma16816(O[2*ntp+1], aph, b1h);
                mma16816(O[2*ntp+1], aph, b1l);
                mma16816(O[2*ntp+1], apl, b1h);
            }
        }
        __syncthreads();
    }

    float inv0 = 1.0f / lrun0, inv1 = 1.0f / lrun1;
    size_t base0 = ((size_t)b * Lk + qrow0) * Ek + h * Dk;
    size_t base1 = ((size_t)b * Lk + qrow1) * Ek + h * Dk;
    #pragma unroll
    for (int nt = 0; nt < 8; nt++) {
        int col = nt * 8 + 2 * tg;
        unsigned hi, lo;
        pack_split(O[nt][0] * inv0, O[nt][1] * inv0, hi, lo);
        *(unsigned*)&g_oh[base0 + col] = hi;
        *(unsigned*)&g_ol[base0 + col] = lo;
        pack_split(O[nt][2] * inv1, O[nt][3] * inv1, hi, lo);
        *(unsigned*)&g_oh[base1 + col] = hi;
        *(unsigned*)&g_ol[base1 + col] = lo;
    }
}

// ---------------------------------------------------------------------------
// Output projection: out[m,n] = sum_k att[m,k] * Wo[n,k] + bo[n].
// 256 thr (8 warps), tile M=128 N=128, k-chunks of 32, 2-stage cp.async,
// pre-split Wo (g_woh/g_wol). Row stride 40 elems (80 B).
// ---------------------------------------------------------------------------
#define OP_STAGE_B 40960   // 4 arrays * 128*40*2 bytes
#define OP_ARR_B   10240   // 128*40*2 bytes

__global__ __launch_bounds__(256) void outproj_kernel(const float* __restrict__ bo,
                                                      float* __restrict__ out) {
    extern __shared__ __align__(16) char dsm[];
    unsigned sbase = smem_u32(dsm);

    int n0 = blockIdx.x * 128;
    int m0 = blockIdx.y * 128;
    int tid = threadIdx.x;
    int warp = tid >> 5, lane = tid & 31;
    int g = lane >> 2, tg = lane & 3;
    int mrow = warp * 16;

    unsigned offA = lane_offA(lane, 80), offB = lane_offB(lane, 80);

    // loader mapping: per array, 512 chunks of 16B; 2 per thread
    int ld_r0 = tid >> 2,       ld_c0 = (tid & 3) * 8;           // chunk tid
    int ld_r1 = (tid + 256) >> 2, ld_c1 = ((tid + 256) & 3) * 8; // chunk tid+256
    const __nv_bfloat16* asrc[2] = {g_oh, g_ol};
    const __nv_bfloat16* bsrc[2] = {g_woh, g_wol};

    float acc[16][4] = {};

    // prologue: stage 0 (kc = 0)
    {
        #pragma unroll
        for (int i = 0; i < 2; i++) {
            size_t ga0 = (size_t)(m0 + ld_r0) * Ek + ld_c0;
            size_t ga1 = (size_t)(m0 + ld_r1) * Ek + ld_c1;
            cp16(sbase + i * OP_ARR_B + ld_r0 * 80 + ld_c0 * 2, asrc[i] + ga0);
            cp16(sbase + i * OP_ARR_B + ld_r1 * 80 + ld_c1 * 2, asrc[i] + ga1);
            size_t gb0 = (size_t)(n0 + ld_r0) * Ek + ld_c0;
            size_t gb1 = (size_t)(n0 + ld_r1) * Ek + ld_c1;
            cp16(sbase + (2 + i) * OP_ARR_B + ld_r0 * 80 + ld_c0 * 2, bsrc[i] + gb0);
            cp16(sbase + (2 + i) * OP_ARR_B + ld_r1 * 80 + ld_c1 * 2, bsrc[i] + gb1);
        }
        cp_commit();
    }

    for (int kt = 0; kt < Ek / 32; kt++) {
        int s = kt & 1;
        if (kt + 1 < Ek / 32) {
            int kc = (kt + 1) * 32;
            unsigned dst = sbase + (1 - s) * OP_STAGE_B;
            #pragma unroll
            for (int i = 0; i < 2; i++) {
                size_t ga0 = (size_t)(m0 + ld_r0) * Ek + kc + ld_c0;
                size_t ga1 = (size_t)(m0 + ld_r1) * Ek + kc + ld_c1;
                cp16(dst + i * OP_ARR_B + ld_r0 * 80 + ld_c0 * 2, asrc[i] + ga0);
                cp16(dst + i * OP_ARR_B + ld_r1 * 80 + ld_c1 * 2, asrc[i] + ga1);
                size_t gb0 = (size_t)(n0 + ld_r0) * Ek + kc + ld_c0;
                size_t gb1 = (size_t)(n0 + ld_r1) * Ek + kc + ld_c1;
                cp16(dst + (2 + i) * OP_ARR_B + ld_r0 * 80 + ld_c0 * 2, bsrc[i] + gb0);
                cp16(dst + (2 + i) * OP_ARR_B + ld_r1 * 80 + ld_c1 * 2, bsrc[i] + gb1);
            }
            cp_commit();
            cp_wait<1>();
        } else {
            cp_wait<0>();
        }
        __syncthreads();

        unsigned Ah_u = sbase + s * OP_STAGE_B + mrow * 80 + offA;
        unsigned Al_u = Ah_u + OP_ARR_B;
        unsigned Bh_u = sbase + s * OP_STAGE_B + 2 * OP_ARR_B + offB;
        unsigned Bl_u = Bh_u + OP_ARR_B;

        #pragma unroll
        for (int ks = 0; ks < 2; ks++) {
            U4 ah4 = ldsm4(Ah_u + ks * 32);
            U4 al4 = ldsm4(Al_u + ks * 32);
            #pragma unroll
            for (int ntp = 0; ntp < 8; ntp++) {
                U4 bh4 = ldsm4(Bh_u + ntp * 1280 + ks * 32);
                U4 bl4 = ldsm4(Bl_u + ntp * 1280 + ks * 32);
                unsigned b0h[2] = {bh4.x, bh4.y}, b1h[2] = {bh4.z, bh4.w};
                unsigned b0l[2] = {bl4.x, bl4.y}, b1l[2] = {bl4.z, bl4.w};
                mma16816(acc[2*ntp],   (unsigned*)&ah4, b0h);
                mma16816(acc[2*ntp],   (unsigned*)&ah4, b0l);
                mma16816(acc[2*ntp],   (unsigned*)&al4, b0h);
                mma16816(acc[2*ntp+1], (unsigned*)&ah4, b1h);
                mma16816(acc[2*ntp+1], (unsigned*)&ah4, b1l);
                mma16816(acc[2*ntp+1], (unsigned*)&al4, b1h);
            }
        }
        __syncthreads();
    }

    #pragma unroll
    for (int nt = 0; nt < 16; nt++) {
        int col = n0 + nt * 8 + 2 * tg;
        float2 bias = *(const float2*)&bo[col];
        float2 o0 = make_float2(acc[nt][0] + bias.x, acc[nt][1] + bias.y);
        float2 o1 = make_float2(acc[nt][2] + bias.x, acc[nt][3] + bias.y);
        *(float2*)&out[(size_t)(m0 + mrow + g) * Ek + col]     = o0;
        *(float2*)&out[(size_t)(m0 + mrow + g + 8) * Ek + col] = o1;
    }
}

// ---------------------------------------------------------------------------
extern "C" void kernel_launch(void* const* d_in, const int* in_sizes, int n_in,
                              void* d_out, int out_size) {
    const float* values = (const float*)d_in[0];
    const float* keys   = (const float*)d_in[1];
    const float* query  = (const float*)d_in[2];
    const int*   mask   = (const int*)d_in[3];
    // d_in[4] = size (scalar), compile-time constant here
    const float* Wv = (const float*)d_in[5];
    const float* Wk = (const float*)d_in[6];
    const float* Wq = (const float*)d_in[7];
    const float* Wo = (const float*)d_in[8];
    const float* bo = (const float*)d_in[9];
    float* out = (float*)d_out;

    static const int PROJ_SMEM = (128 * 72 * 2 + 64 * 72 * 2) * (int)sizeof(__nv_bfloat16); // 55296
    static const int ATTN_SMEM = 2 * AT_STAGE_B;   // 73728
    static const int OP_SMEM   = 2 * OP_STAGE_B;   // 81920
    cudaFuncSetAttribute(proj_kernel,    cudaFuncAttributeMaxDynamicSharedMemorySize, PROJ_SMEM);
    cudaFuncSetAttribute(attn_kernel,    cudaFuncAttributeMaxDynamicSharedMemorySize, ATTN_SMEM);
    cudaFuncSetAttribute(outproj_kernel, cudaFuncAttributeMaxDynamicSharedMemorySize, OP_SMEM);

    split_wo_kernel<<<Ek * Ek / 1024, 256>>>(Wo);

    dim3 pgrid(Lk / 128, Bk * Hk, 3);
    proj_kernel<<<pgrid, 256, PROJ_SMEM>>>(values, keys, query, Wv, Wk, Wq);

    dim3 agrid(Lk / 256, Bk * Hk);
    attn_kernel<<<agrid, 512, ATTN_SMEM>>>(mask);

    dim3 ogrid(Ek / 128, BLk / 128);
    outproj_kernel<<<ogrid, 256, OP_SMEM>>>(bo, out);
}

// round 16
// speedup vs baseline: 5.5521x; 1.0058x over previous
#include <cuda_runtime.h>
#include <cuda_bf16.h>

#define Bk 8
#define Lk 1024
#define Ek 1024
#define Hk 16
#define Dk 64
#define BLk (Bk*Lk)

// hi/lo bf16 scratch (device globals — no allocation in kernel_launch)
__device__ __nv_bfloat16 g_qh[(size_t)Bk*Lk*Ek], g_ql[(size_t)Bk*Lk*Ek];
__device__ __nv_bfloat16 g_kh[(size_t)Bk*Lk*Ek], g_kl[(size_t)Bk*Lk*Ek];
__device__ __nv_bfloat16 g_vh[(size_t)Bk*Lk*Ek], g_vl[(size_t)Bk*Lk*Ek];
__device__ __nv_bfloat16 g_oh[(size_t)Bk*Lk*Ek], g_ol[(size_t)Bk*Lk*Ek];
__device__ __nv_bfloat16 g_woh[(size_t)Ek*Ek],   g_wol[(size_t)Ek*Ek];

// ---------------------------------------------------------------------------
__device__ __forceinline__ void mma16816(float* d, const unsigned* a, const unsigned* b) {
    asm volatile(
        "mma.sync.aligned.m16n8k16.row.col.f32.bf16.bf16.f32 "
        "{%0,%1,%2,%3}, {%4,%5,%6,%7}, {%8,%9}, {%0,%1,%2,%3};\n"
        : "+f"(d[0]), "+f"(d[1]), "+f"(d[2]), "+f"(d[3])
        : "r"(a[0]), "r"(a[1]), "r"(a[2]), "r"(a[3]), "r"(b[0]), "r"(b[1]));
}

struct U4 { unsigned x, y, z, w; };

__device__ __forceinline__ U4 ldsm4(unsigned addr) {
    U4 r;
    asm volatile("ldmatrix.sync.aligned.m8n8.x4.shared.b16 {%0,%1,%2,%3}, [%4];\n"
                 : "=r"(r.x), "=r"(r.y), "=r"(r.z), "=r"(r.w) : "r"(addr));
    return r;
}
__device__ __forceinline__ U4 ldsm4t(unsigned addr) {
    U4 r;
    asm volatile("ldmatrix.sync.aligned.m8n8.x4.trans.shared.b16 {%0,%1,%2,%3}, [%4];\n"
                 : "=r"(r.x), "=r"(r.y), "=r"(r.z), "=r"(r.w) : "r"(addr));
    return r;
}
__device__ __forceinline__ unsigned smem_u32(const void* p) {
    return (unsigned)__cvta_generic_to_shared(p);
}
__device__ __forceinline__ void cp16(unsigned smem_dst, const void* gsrc) {
    asm volatile("cp.async.cg.shared.global [%0], [%1], 16;\n" :: "r"(smem_dst), "l"(gsrc));
}
__device__ __forceinline__ void cp_commit() { asm volatile("cp.async.commit_group;\n"); }
template <int N> __device__ __forceinline__ void cp_wait() {
    asm volatile("cp.async.wait_group %0;\n" :: "n"(N));
}

// per-lane byte offsets into a tile with given row stride (bytes)
__device__ __forceinline__ unsigned lane_offA(int l, int strideB) {
    return ((l & 7) + ((l >> 3) & 1) * 8) * (unsigned)strideB + ((l >> 4) & 1) * 16u;
}
__device__ __forceinline__ unsigned lane_offB(int l, int strideB) {
    return ((l & 7) + ((l >> 4) & 1) * 8) * (unsigned)strideB + ((l >> 3) & 1) * 16u;
}

__device__ __forceinline__ void split1(float x, __nv_bfloat16& h, __nv_bfloat16& l) {
    h = __float2bfloat16_rn(x);
    l = __float2bfloat16_rn(x - __bfloat162float(h));
}
__device__ __forceinline__ void pack_split(float x, float y, unsigned& hi, unsigned& lo) {
    __nv_bfloat162 h = __floats2bfloat162_rn(x, y);
    float rx = x - __bfloat162float(h.x);
    float ry = y - __bfloat162float(h.y);
    __nv_bfloat162 l = __floats2bfloat162_rn(rx, ry);
    hi = *(unsigned*)&h; lo = *(unsigned*)&l;
}

// ---------------------------------------------------------------------------
// Pre-split Wo (fp32 -> hi/lo bf16), once per launch. 1M elems.
// ---------------------------------------------------------------------------
__global__ __launch_bounds__(256) void split_wo_kernel(const float* __restrict__ Wo) {
    int slot = blockIdx.x * 256 + threadIdx.x;     // float4 slot
    float4 w = *(const float4*)&Wo[(size_t)slot * 4];
    __nv_bfloat16 h0, l0, h1, l1, h2, l2, h3, l3;
    split1(w.x, h0, l0); split1(w.y, h1, l1);
    split1(w.z, h2, l2); split1(w.w, h3, l3);
    __nv_bfloat16 hv[4] = {h0, h1, h2, h3}, lv[4] = {l0, l1, l2, l3};
    *(uint2*)&g_woh[(size_t)slot * 4] = *(uint2*)hv;
    *(uint2*)&g_wol[(size_t)slot * 4] = *(uint2*)lv;
}

// ---------------------------------------------------------------------------
// Per-head projection: 128-row blocks, 8 warps, tile M=128 N=64 K=64.
// which = blockIdx.z: 0=q, 1=k, 2=v. Writes hi/lo bf16 pairs to global.
// ---------------------------------------------------------------------------
__global__ __launch_bounds__(256) void proj_kernel(const float* __restrict__ vin,
                                                   const float* __restrict__ kin,
                                                   const float* __restrict__ qin,
                                                   const float* __restrict__ Wv,
                                                   const float* __restrict__ Wk,
                                                   const float* __restrict__ Wq) {
    extern __shared__ __align__(16) char dsm[];
    __nv_bfloat16* Xh = (__nv_bfloat16*)dsm;            // 128*72
    __nv_bfloat16* Xl = Xh + 128 * 72;
    __nv_bfloat16* Wh = Xl + 128 * 72;                  // 64*72
    __nv_bfloat16* Wl = Wh + 64 * 72;

    int which = blockIdx.z;
    const float* in = (which == 0) ? qin : (which == 1) ? kin : vin;
    const float* W  = (which == 0) ? Wq  : (which == 1) ? Wk  : Wv;
    __nv_bfloat16* outh = (which == 0) ? g_qh : (which == 1) ? g_kh : g_vh;
    __nv_bfloat16* outl = (which == 0) ? g_ql : (which == 1) ? g_kl : g_vl;

    int bh = blockIdx.y;
    int b = bh >> 4, h = bh & 15;
    int l0 = blockIdx.x * 128;
    int tid = threadIdx.x;
    int warp = tid >> 5, lane = tid & 31;
    int g = lane >> 2, tg = lane & 3;

    const float* inp = in + ((size_t)b * Lk + l0) * Ek + h * Dk;
    const float* Wp  = W + (size_t)h * Dk * Dk;

    #pragma unroll
    for (int i = 0; i < 8; i++) {
        int slot = tid + 256 * i;            // 2048 float4 slots (128x64)
        int r = slot >> 4, c = (slot & 15) * 4;
        float4 x = *(const float4*)&inp[(size_t)r * Ek + c];
        split1(x.x, Xh[r*72+c+0], Xl[r*72+c+0]);
        split1(x.y, Xh[r*72+c+1], Xl[r*72+c+1]);
        split1(x.z, Xh[r*72+c+2], Xl[r*72+c+2]);
        split1(x.w, Xh[r*72+c+3], Xl[r*72+c+3]);
    }
    #pragma unroll
    for (int i = 0; i < 4; i++) {
        int slot = tid + 256 * i;            // 1024 float4 slots (64x64)
        int r = slot >> 4, c = (slot & 15) * 4;
        float4 w = *(const float4*)&Wp[r * 64 + c];
        split1(w.x, Wh[r*72+c+0], Wl[r*72+c+0]);
        split1(w.y, Wh[r*72+c+1], Wl[r*72+c+1]);
        split1(w.z, Wh[r*72+c+2], Wl[r*72+c+2]);
        split1(w.w, Wh[r*72+c+3], Wl[r*72+c+3]);
    }
    __syncthreads();

    int mrow = warp * 16;
    unsigned offA = lane_offA(lane, 144), offB = lane_offB(lane, 144);
    unsigned Xh_u = smem_u32(Xh) + mrow * 144 + offA;
    unsigned Xl_u = smem_u32(Xl) + mrow * 144 + offA;
    unsigned Wh_u = smem_u32(Wh) + offB;
    unsigned Wl_u = smem_u32(Wl) + offB;

    U4 ah[4], al[4];
    #pragma unroll
    for (int ks = 0; ks < 4; ks++) {
        ah[ks] = ldsm4(Xh_u + ks * 32);
        al[ks] = ldsm4(Xl_u + ks * 32);
    }

    float acc[8][4] = {};
    #pragma unroll
    for (int ks = 0; ks < 4; ks++) {
        #pragma unroll
        for (int ntp = 0; ntp < 4; ntp++) {
            U4 bh4 = ldsm4(Wh_u + ntp * 2304 + ks * 32);
            U4 bl4 = ldsm4(Wl_u + ntp * 2304 + ks * 32);
            unsigned b0h[2] = {bh4.x, bh4.y}, b1h[2] = {bh4.z, bh4.w};
            unsigned b0l[2] = {bl4.x, bl4.y}, b1l[2] = {bl4.z, bl4.w};
            mma16816(acc[2*ntp],   (unsigned*)&ah[ks], b0h);
            mma16816(acc[2*ntp],   (unsigned*)&ah[ks], b0l);
            mma16816(acc[2*ntp],   (unsigned*)&al[ks], b0h);
            mma16816(acc[2*ntp+1], (unsigned*)&ah[ks], b1h);
            mma16816(acc[2*ntp+1], (unsigned*)&ah[ks], b1l);
            mma16816(acc[2*ntp+1], (unsigned*)&al[ks], b1h);
        }
    }

    size_t base0 = ((size_t)b * Lk + l0 + mrow + g) * Ek + h * Dk;
    size_t base1 = base0 + (size_t)8 * Ek;
    #pragma unroll
    for (int nt = 0; nt < 8; nt++) {
        int col = nt * 8 + 2 * tg;
        unsigned hi, lo;
        pack_split(acc[nt][0], acc[nt][1], hi, lo);
        *(unsigned*)&outh[base0 + col] = hi;
        *(unsigned*)&outl[base0 + col] = lo;
        pack_split(acc[nt][2], acc[nt][3], hi, lo);
        *(unsigned*)&outh[base1 + col] = hi;
        *(unsigned*)&outl[base1 + col] = lo;
    }
}

// ---------------------------------------------------------------------------
// Flash attention: 512 thr (16 warps), q-tile 256 (m16/warp), k-tiles of 64.
// 3-stage cp.async pipeline, single __syncthreads per k-tile.
// ---------------------------------------------------------------------------
#define AT_STAGE_B 36864   // 4 arrays * 64*72*2 bytes
#define AT_ARR_B   9216    // 64*72*2 bytes
#define AT_NT      (Lk/64)

__global__ __launch_bounds__(512) void attn_kernel(const int* __restrict__ mask) {
    extern __shared__ __align__(16) char dsm[];
    unsigned sbase = smem_u32(dsm);

    int bh = blockIdx.y;
    int b = bh >> 4, h = bh & 15;
    int q0 = blockIdx.x * 256;
    int tid = threadIdx.x;
    int warp = tid >> 5, lane = tid & 31;
    int g = lane >> 2, tg = lane & 3;
    const float scale = 0.125f;

    int mrow = warp * 16;
    int qrow0 = q0 + mrow + g;
    int qrow1 = qrow0 + 8;

    // Q fragments directly from global (once per block)
    unsigned qfh[4][4], qfl[4][4];
    {
        size_t qb = ((size_t)b * Lk + qrow0) * Ek + h * Dk;
        #pragma unroll
        for (int ks = 0; ks < 4; ks++) {
            int c = ks * 16 + 2 * tg;
            qfh[ks][0] = *(const unsigned*)&g_qh[qb + c];
            qfh[ks][1] = *(const unsigned*)&g_qh[qb + 8 * Ek + c];
            qfh[ks][2] = *(const unsigned*)&g_qh[qb + c + 8];
            qfh[ks][3] = *(const unsigned*)&g_qh[qb + 8 * Ek + c + 8];
            qfl[ks][0] = *(const unsigned*)&g_ql[qb + c];
            qfl[ks][1] = *(const unsigned*)&g_ql[qb + 8 * Ek + c];
            qfl[ks][2] = *(const unsigned*)&g_ql[qb + c + 8];
            qfl[ks][3] = *(const unsigned*)&g_ql[qb + 8 * Ek + c + 8];
        }
    }

    unsigned offA = lane_offA(lane, 144), offB = lane_offB(lane, 144);

    float mrun0 = -1e30f, mrun1 = -1e30f, lrun0 = 0.f, lrun1 = 0.f;
    float O[8][4] = {};
    const int* mb = mask + (size_t)b * Lk * Lk;

    // loader: 4 chunks of 16B per thread per tile
    const __nv_bfloat16* srcs[4] = {g_kh, g_kl, g_vh, g_vl};
    int ld_r = tid >> 3;                 // 0..63
    int ld_c = (tid & 7) * 8;            // element col (8 bf16 = 16 B)
    unsigned ld_off = (unsigned)(ld_r * 144 + ld_c * 2);
    size_t ld_g = (size_t)b * Lk * Ek + h * Dk + (size_t)ld_r * Ek + ld_c;

    #pragma unroll 1
    for (int pk = 0; pk < 2; pk++) {       // prologue: tiles 0,1
        unsigned dst = sbase + pk * AT_STAGE_B + ld_off;
        size_t gb = ld_g + (size_t)pk * 64 * Ek;
        #pragma unroll
        for (int i = 0; i < 4; i++)
            cp16(dst + i * AT_ARR_B, srcs[i] + gb);
        cp_commit();
    }

    for (int kt = 0; kt < AT_NT; kt++) {
        int s = kt % 3;
        if (kt == AT_NT - 1) cp_wait<0>(); else cp_wait<1>();
        __syncthreads();
        if (kt + 2 < AT_NT) {
            unsigned dst = sbase + ((kt + 2) % 3) * AT_STAGE_B + ld_off;
            size_t gb = ld_g + (size_t)(kt + 2) * 64 * Ek;
            #pragma unroll
            for (int i = 0; i < 4; i++)
                cp16(dst + i * AT_ARR_B, srcs[i] + gb);
            cp_commit();
        }

        unsigned Kh_u = sbase + s * AT_STAGE_B + offB;
        unsigned Kl_u = Kh_u + AT_ARR_B;
        unsigned Vh_u = sbase + s * AT_STAGE_B + 2 * AT_ARR_B + offA;
        unsigned Vl_u = Vh_u + AT_ARR_B;
        int k0 = kt * 64;

        // ---- S = Q @ K^T (bf16x3) ----
        float sc[8][4] = {};
        #pragma unroll
        for (int ks = 0; ks < 4; ks++) {
            #pragma unroll
            for (int ntp = 0; ntp < 4; ntp++) {
                U4 bh4 = ldsm4(Kh_u + ntp * 2304 + ks * 32);
                U4 bl4 = ldsm4(Kl_u + ntp * 2304 + ks * 32);
                unsigned b0h[2] = {bh4.x, bh4.y}, b1h[2] = {bh4.z, bh4.w};
                unsigned b0l[2] = {bl4.x, bl4.y}, b1l[2] = {bl4.z, bl4.w};
                mma16816(sc[2*ntp],   qfh[ks], b0h);
                mma16816(sc[2*ntp],   qfh[ks], b0l);
                mma16816(sc[2*ntp],   qfl[ks], b0h);
                mma16816(sc[2*ntp+1], qfh[ks], b1h);
                mma16816(sc[2*ntp+1], qfh[ks], b1l);
                mma16816(sc[2*ntp+1], qfl[ks], b1h);
            }
        }

        // ---- mask + scale ----
        #pragma unroll
        for (int nt = 0; nt < 8; nt++) {
            int col = k0 + nt * 8 + 2 * tg;
            int2 m0 = *(const int2*)&mb[(size_t)qrow0 * Lk + col];
            int2 m1 = *(const int2*)&mb[(size_t)qrow1 * Lk + col];
            sc[nt][0] = m0.x ? sc[nt][0] * scale : -1e20f;
            sc[nt][1] = m0.y ? sc[nt][1] * scale : -1e20f;
            sc[nt][2] = m1.x ? sc[nt][2] * scale : -1e20f;
            sc[nt][3] = m1.y ? sc[nt][3] * scale : -1e20f;
        }

        // ---- online softmax ----
        float mx0 = -1e30f, mx1 = -1e30f;
        #pragma unroll
        for (int nt = 0; nt < 8; nt++) {
            mx0 = fmaxf(mx0, fmaxf(sc[nt][0], sc[nt][1]));
            mx1 = fmaxf(mx1, fmaxf(sc[nt][2], sc[nt][3]));
        }
        mx0 = fmaxf(mx0, __shfl_xor_sync(0xffffffffu, mx0, 1));
        mx0 = fmaxf(mx0, __shfl_xor_sync(0xffffffffu, mx0, 2));
        mx1 = fmaxf(mx1, __shfl_xor_sync(0xffffffffu, mx1, 1));
        mx1 = fmaxf(mx1, __shfl_xor_sync(0xffffffffu, mx1, 2));

        float mn0 = fmaxf(mrun0, mx0), mn1 = fmaxf(mrun1, mx1);
        float a0 = __expf(mrun0 - mn0), a1 = __expf(mrun1 - mn1);
        mrun0 = mn0; mrun1 = mn1;

        float rs0 = 0.f, rs1 = 0.f;
        #pragma unroll
        for (int nt = 0; nt < 8; nt++) {
            sc[nt][0] = __expf(sc[nt][0] - mn0);
            sc[nt][1] = __expf(sc[nt][1] - mn0);
            sc[nt][2] = __expf(sc[nt][2] - mn1);
            sc[nt][3] = __expf(sc[nt][3] - mn1);
            rs0 += sc[nt][0] + sc[nt][1];
            rs1 += sc[nt][2] + sc[nt][3];
        }
        rs0 += __shfl_xor_sync(0xffffffffu, rs0, 1);
        rs0 += __shfl_xor_sync(0xffffffffu, rs0, 2);
        rs1 += __shfl_xor_sync(0xffffffffu, rs1, 1);
        rs1 += __shfl_xor_sync(0xffffffffu, rs1, 2);
        lrun0 = lrun0 * a0 + rs0;
        lrun1 = lrun1 * a1 + rs1;

        #pragma unroll
        for (int nt = 0; nt < 8; nt++) {
            O[nt][0] *= a0; O[nt][1] *= a0;
            O[nt][2] *= a1; O[nt][3] *= a1;
        }

        // ---- O += P @ V ----
        #pragma unroll
        for (int ks = 0; ks < 4; ks++) {
            unsigned aph[4], apl[4];
            pack_split(sc[2*ks][0],   sc[2*ks][1],   aph[0], apl[0]);
            pack_split(sc[2*ks][2],   sc[2*ks][3],   aph[1], apl[1]);
            pack_split(sc[2*ks+1][0], sc[2*ks+1][1], aph[2], apl[2]);
            pack_split(sc[2*ks+1][2], sc[2*ks+1][3], aph[3], apl[3]);
            #pragma unroll
            for (int ntp = 0; ntp < 4; ntp++) {
                U4 vh4 = ldsm4t(Vh_u + ks * 2304 + ntp * 32);
                U4 vl4 = ldsm4t(Vl_u + ks * 2304 + ntp * 32);
                unsigned b0h[2] = {vh4.x, vh4.y}, b1h[2] = {vh4.z, vh4.w};
                unsigned b0l[2] = {vl4.x, vl4.y}, b1l[2] = {vl4.z, vl4.w};
                mma16816(O[2*ntp],   aph, b0h);
                mma16816(O[2*ntp],   aph, b0l);
                mma16816(O[2*ntp],   apl, b0h);
                mma16816(O[2*ntp+1], aph, b1h);
                mma16816(O[2*ntp+1], aph, b1l);
                mma16816(O[2*ntp+1], apl, b1h);
            }
        }
    }

    float inv0 = 1.0f / lrun0, inv1 = 1.0f / lrun1;
    size_t base0 = ((size_t)b * Lk + qrow0) * Ek + h * Dk;
    size_t base1 = ((size_t)b * Lk + qrow1) * Ek + h * Dk;
    #pragma unroll
    for (int nt = 0; nt < 8; nt++) {
        int col = nt * 8 + 2 * tg;
        unsigned hi, lo;
        pack_split(O[nt][0] * inv0, O[nt][1] * inv0, hi, lo);
        *(unsigned*)&g_oh[base0 + col] = hi;
        *(unsigned*)&g_ol[base0 + col] = lo;
        pack_split(O[nt][2] * inv1, O[nt][3] * inv1, hi, lo);
        *(unsigned*)&g_oh[base1 + col] = hi;
        *(unsigned*)&g_ol[base1 + col] = lo;
    }
}

// ---------------------------------------------------------------------------
// Output projection: out[m,n] = sum_k att[m,k] * Wo[n,k] + bo[n].
// 512 thr (16 warps), tile M=256 N=128, k-chunks of 32, 3-stage cp.async,
// single sync per iter. Row stride 40 elems (80 B).
// ---------------------------------------------------------------------------
#define OP_ARR_A  20480    // 256*40*2
#define OP_ARR_B  10240    // 128*40*2
#define OP_STG    61440    // 2*ARR_A + 2*ARR_B
#define OP_NT     (Ek/32)

__global__ __launch_bounds__(512) void outproj_kernel(const float* __restrict__ bo,
                                                      float* __restrict__ out) {
    extern __shared__ __align__(16) char dsm[];
    unsigned sbase = smem_u32(dsm);

    int n0 = blockIdx.x * 128;
    int m0 = blockIdx.y * 256;
    int tid = threadIdx.x;
    int warp = tid >> 5, lane = tid & 31;
    int g = lane >> 2, tg = lane & 3;
    int mrow = warp * 16;

    unsigned offA = lane_offA(lane, 80), offB = lane_offB(lane, 80);

    // loader mapping: A has 1024 16B-chunks per array (2/thread), B has 512 (1/thread)
    int a_r0 = tid >> 2,          a_c0 = (tid & 3) * 8;
    int a_r1 = (tid + 512) >> 2,  a_c1 = ((tid + 512) & 3) * 8;
    int b_r  = tid >> 2,          b_c  = (tid & 3) * 8;

    float acc[16][4] = {};

    #pragma unroll 1
    for (int pk = 0; pk < 2; pk++) {       // prologue: k-chunks 0,1
        unsigned dst = sbase + pk * OP_STG;
        int kc = pk * 32;
        cp16(dst + a_r0 * 80 + a_c0 * 2,            g_oh  + (size_t)(m0 + a_r0) * Ek + kc + a_c0);
        cp16(dst + a_r1 * 80 + a_c1 * 2,            g_oh  + (size_t)(m0 + a_r1) * Ek + kc + a_c1);
        cp16(dst + OP_ARR_A + a_r0 * 80 + a_c0 * 2, g_ol  + (size_t)(m0 + a_r0) * Ek + kc + a_c0);
        cp16(dst + OP_ARR_A + a_r1 * 80 + a_c1 * 2, g_ol  + (size_t)(m0 + a_r1) * Ek + kc + a_c1);
        cp16(dst + 2*OP_ARR_A + b_r * 80 + b_c * 2,            g_woh + (size_t)(n0 + b_r) * Ek + kc + b_c);
        cp16(dst + 2*OP_ARR_A + OP_ARR_B + b_r * 80 + b_c * 2, g_wol + (size_t)(n0 + b_r) * Ek + kc + b_c);
        cp_commit();
    }

    for (int kt = 0; kt < OP_NT; kt++) {
        int s = kt % 3;
        if (kt == OP_NT - 1) cp_wait<0>(); else cp_wait<1>();
        __syncthreads();
        if (kt + 2 < OP_NT) {
            unsigned dst = sbase + ((kt + 2) % 3) * OP_STG;
            int kc = (kt + 2) * 32;
            cp16(dst + a_r0 * 80 + a_c0 * 2,            g_oh  + (size_t)(m0 + a_r0) * Ek + kc + a_c0);
            cp16(dst + a_r1 * 80 + a_c1 * 2,            g_oh  + (size_t)(m0 + a_r1) * Ek + kc + a_c1);
            cp16(dst + OP_ARR_A + a_r0 * 80 + a_c0 * 2, g_ol  + (size_t)(m0 + a_r0) * Ek + kc + a_c0);
            cp16(dst + OP_ARR_A + a_r1 * 80 + a_c1 * 2, g_ol  + (size_t)(m0 + a_r1) * Ek + kc + a_c1);
            cp16(dst + 2*OP_ARR_A + b_r * 80 + b_c * 2,            g_woh + (size_t)(n0 + b_r) * Ek + kc + b_c);
            cp16(dst + 2*OP_ARR_A + OP_ARR_B + b_r * 80 + b_c * 2, g_wol + (size_t)(n0 + b_r) * Ek + kc + b_c);
            cp_commit();
        }

        unsigned Ah_u = sbase + s * OP_STG + mrow * 80 + offA;
        unsigned Al_u = Ah_u + OP_ARR_A;
        unsigned Bh_u = sbase + s * OP_STG + 2 * OP_ARR_A + offB;
        unsigned Bl_u = Bh_u + OP_ARR_B;

        #pragma unroll
        for (int ks = 0; ks < 2; ks++) {
            U4 ah4 = ldsm4(Ah_u + ks * 32);
            U4 al4 = ldsm4(Al_u + ks * 32);
            #pragma unroll
            for (int ntp = 0; ntp < 8; ntp++) {
                U4 bh4 = ldsm4(Bh_u + ntp * 1280 + ks * 32);
                U4 bl4 = ldsm4(Bl_u + ntp * 1280 + ks * 32);
                unsigned b0h[2] = {bh4.x, bh4.y}, b1h[2] = {bh4.z, bh4.w};
                unsigned b0l[2] = {bl4.x, bl4.y}, b1l[2] = {bl4.z, bl4.w};
                mma16816(acc[2*ntp],   (unsigned*)&ah4, b0h);
                mma16816(acc[2*ntp],   (unsigned*)&ah4, b0l);
                mma16816(acc[2*ntp],   (unsigned*)&al4, b0h);
                mma16816(acc[2*ntp+1], (unsigned*)&ah4, b1h);
                mma16816(acc[2*ntp+1], (unsigned*)&ah4, b1l);
                mma16816(acc[2*ntp+1], (unsigned*)&al4, b1h);
            }
        }
    }

    #pragma unroll
    for (int nt = 0; nt < 16; nt++) {
        int col = n0 + nt * 8 + 2 * tg;
        float2 bias = *(const float2*)&bo[col];
        float2 o0 = make_float2(acc[nt][0] + bias.x, acc[nt][1] + bias.y);
        float2 o1 = make_float2(acc[nt][2] + bias.x, acc[nt][3] + bias.y);
        *(float2*)&out[(size_t)(m0 + mrow + g) * Ek + col]     = o0;
        *(float2*)&out[(size_t)(m0 + mrow + g + 8) * Ek + col] = o1;
    }
}

// ---------------------------------------------------------------------------
extern "C" void kernel_launch(void* const* d_in, const int* in_sizes, int n_in,
                              void* d_out, int out_size) {
    const float* values = (const float*)d_in[0];
    const float* keys   = (const float*)d_in[1];
    const float* query  = (const float*)d_in[2];
    const int*   mask   = (const int*)d_in[3];
    // d_in[4] = size (scalar), compile-time constant here
    const float* Wv = (const float*)d_in[5];
    const float* Wk = (const float*)d_in[6];
    const float* Wq = (const float*)d_in[7];
    const float* Wo = (const float*)d_in[8];
    const float* bo = (const float*)d_in[9];
    float* out = (float*)d_out;

    static const int PROJ_SMEM = (128 * 72 * 2 + 64 * 72 * 2) * (int)sizeof(__nv_bfloat16); // 55296
    static const int ATTN_SMEM = 3 * AT_STAGE_B;   // 110592
    static const int OP_SMEM   = 3 * OP_STG;       // 184320
    cudaFuncSetAttribute(proj_kernel,    cudaFuncAttributeMaxDynamicSharedMemorySize, PROJ_SMEM);
    cudaFuncSetAttribute(attn_kernel,    cudaFuncAttributeMaxDynamicSharedMemorySize, ATTN_SMEM);
    cudaFuncSetAttribute(outproj_kernel, cudaFuncAttributeMaxDynamicSharedMemorySize, OP_SMEM);

    split_wo_kernel<<<Ek * Ek / 1024, 256>>>(Wo);

    dim3 pgrid(Lk / 128, Bk * Hk, 3);
    proj_kernel<<<pgrid, 256, PROJ_SMEM>>>(values, keys, query, Wv, Wk, Wq);

    dim3 agrid(Lk / 256, Bk * Hk);
    attn_kernel<<<agrid, 512, ATTN_SMEM>>>(mask);

    dim3 ogrid(Ek / 128, BLk / 256);
    outproj_kernel<<<ogrid, 512, OP_SMEM>>>(bo, out);
}